// round 5
// baseline (speedup 1.0000x reference)
#include <cuda_runtime.h>
#include <cuda_bf16.h>
#include <cuda_fp16.h>
#include <cstdint>
#include <math.h>

#define N_NODES 40000
#define N_EDGES 640000
#define D 128
#define R 32
#define NB 8

// ---- scratch (static device globals; no runtime allocation) ----
__device__ __half g_xbh[(size_t)N_NODES * NB * D];  // 82 MB: bases 0-7, fp16
__device__ float g_xloop[(size_t)N_NODES * D];      // 20.5 MB: loop block fp32
__device__ float g_s[(size_t)N_NODES * R];          // 5.1 MB
__device__ float g_attdot[(size_t)N_NODES * NB];    // 1.28 MB
__device__ float g_ex[N_EDGES];
__device__ float g_denom[N_NODES];
__device__ float g_accum[(size_t)N_NODES * D];      // 20.5 MB
__device__ float g_ft[(size_t)N_NODES * D];         // 20.5 MB
__device__ float g_colsum[D];
__device__ float g_colsumsq[D];
__device__ float g_scale[D];
__device__ float g_shift[D];
__device__ __nv_bfloat16 g_xhi[(size_t)N_NODES * D];
__device__ __nv_bfloat16 g_xlo[(size_t)N_NODES * D];
__device__ __nv_bfloat16 g_wthi[9 * D * D];         // [b][n][k]  (W^T, k contiguous)
__device__ __nv_bfloat16 g_wtlo[9 * D * D];
// CSR by src
__device__ int g_cnt[N_NODES];
__device__ int g_cur[N_NODES];
__device__ int g_off[N_NODES + 1];
__device__ int g_pk2[N_EDGES];    // dst*32 + rel
__device__ int g_eid2[N_EDGES];   // original edge id

// ================= conversion kernels =================
__global__ void k_convx(const float* __restrict__ x) {
    int i = blockIdx.x * blockDim.x + threadIdx.x;
    if (i >= N_NODES * D) return;
    float v = x[i];
    __nv_bfloat16 h = __float2bfloat16(v);
    g_xhi[i] = h;
    g_xlo[i] = __float2bfloat16(v - __bfloat162float(h));
}

__global__ void k_convw(const float* __restrict__ w_bases, const float* __restrict__ w_loop) {
    int i = blockIdx.x * blockDim.x + threadIdx.x;
    if (i >= 9 * D * D) return;
    int b = i >> 14;
    int rem = i & 16383;
    int n = rem >> 7;
    int k = rem & 127;
    float v = (b < 8) ? w_bases[(b << 14) + k * D + n] : w_loop[k * D + n];
    __nv_bfloat16 h = __float2bfloat16(v);
    g_wthi[i] = h;
    g_wtlo[i] = __float2bfloat16(v - __bfloat162float(h));
}

// ================= mma.sync bf16 GEMM, 64x64 warp tiles =================
// Grid: (313 m-tiles, 9 bases). CTA = 128 thr = 4 warps (2 m x 2 n).

#define PAD 40

__global__ __launch_bounds__(128) void k_gemm_mma(const float* __restrict__ att) {
    __shared__ __align__(16) __nv_bfloat16 Ah[128 * PAD];
    __shared__ __align__(16) __nv_bfloat16 Al[128 * PAD];
    __shared__ __align__(16) __nv_bfloat16 Bh[128 * PAD];
    __shared__ __align__(16) __nv_bfloat16 Bl[128 * PAD];
    __shared__ float atts[128];

    const int tid = threadIdx.x;
    const int lane = tid & 31;
    const int wid = tid >> 5;
    const int wm = wid & 1;       // 2 m-strips of 64
    const int wn = wid >> 1;      // 2 n-strips of 64
    const int m0 = blockIdx.x * 128;
    const int b = blockIdx.y;

    atts[tid] = att[tid];

    float acc[4][8][4];
#pragma unroll
    for (int mf = 0; mf < 4; mf++)
#pragma unroll
        for (int nf = 0; nf < 8; nf++)
#pragma unroll
            for (int r = 0; r < 4; r++) acc[mf][nf][r] = 0.f;

    const int a_row = wm * 64 + (lane & 15);
    const int a_cb = (lane >> 4) << 3;
    const int b_row = wn * 64 + (lane & 7) + ((lane >> 4) << 3);
    const int b_cb = (lane & 8);

    const __nv_bfloat16* Bgh = g_wthi + b * (D * D);
    const __nv_bfloat16* Bgl = g_wtlo + b * (D * D);

#pragma unroll 1
    for (int kc = 0; kc < 4; kc++) {
        const int k0 = kc * 32;
        __syncthreads();
#pragma unroll
        for (int l = 0; l < 4; l++) {
            int i = l * 128 + tid;          // 0..511 per tile
            int row = i >> 2;
            int c8 = (i & 3) * 8;
            int g = m0 + row;
            uint4 vh = make_uint4(0, 0, 0, 0), vl = make_uint4(0, 0, 0, 0);
            if (g < N_NODES) {
                vh = *(const uint4*)(g_xhi + (size_t)g * D + k0 + c8);
                vl = *(const uint4*)(g_xlo + (size_t)g * D + k0 + c8);
            }
            *(uint4*)(Ah + row * PAD + c8) = vh;
            *(uint4*)(Al + row * PAD + c8) = vl;
            *(uint4*)(Bh + row * PAD + c8) = *(const uint4*)(Bgh + row * D + k0 + c8);
            *(uint4*)(Bl + row * PAD + c8) = *(const uint4*)(Bgl + row * D + k0 + c8);
        }
        __syncthreads();
#pragma unroll
        for (int ks = 0; ks < 2; ks++) {
            const int kk = ks * 16;
            uint32_t ah[4][4], bh[8][2];
#pragma unroll
            for (int mf = 0; mf < 4; mf++) {
                uint32_t addr = (uint32_t)__cvta_generic_to_shared(
                    Ah + (a_row + mf * 16) * PAD + kk + a_cb);
                asm volatile("ldmatrix.sync.aligned.m8n8.x4.shared.b16 {%0,%1,%2,%3}, [%4];"
                    : "=r"(ah[mf][0]), "=r"(ah[mf][1]), "=r"(ah[mf][2]), "=r"(ah[mf][3])
                    : "r"(addr));
            }
#pragma unroll
            for (int nf2 = 0; nf2 < 4; nf2++) {
                uint32_t addr = (uint32_t)__cvta_generic_to_shared(
                    Bh + (b_row + nf2 * 16) * PAD + kk + b_cb);
                asm volatile("ldmatrix.sync.aligned.m8n8.x4.shared.b16 {%0,%1,%2,%3}, [%4];"
                    : "=r"(bh[nf2 * 2][0]), "=r"(bh[nf2 * 2][1]),
                      "=r"(bh[nf2 * 2 + 1][0]), "=r"(bh[nf2 * 2 + 1][1])
                    : "r"(addr));
            }
#define MMA(ar, br) \
    asm volatile("mma.sync.aligned.m16n8k16.row.col.f32.bf16.bf16.f32 " \
        "{%0,%1,%2,%3}, {%4,%5,%6,%7}, {%8,%9}, {%0,%1,%2,%3};" \
        : "+f"(acc[mf][nf][0]), "+f"(acc[mf][nf][1]), \
          "+f"(acc[mf][nf][2]), "+f"(acc[mf][nf][3]) \
        : "r"((ar)[0]), "r"((ar)[1]), "r"((ar)[2]), "r"((ar)[3]), \
          "r"((br)[0]), "r"((br)[1]))
            // hh
#pragma unroll
            for (int mf = 0; mf < 4; mf++)
#pragma unroll
                for (int nf = 0; nf < 8; nf++) MMA(ah[mf], bh[nf]);
            // lh: al x bh
            {
                uint32_t al[4][4];
#pragma unroll
                for (int mf = 0; mf < 4; mf++) {
                    uint32_t addr = (uint32_t)__cvta_generic_to_shared(
                        Al + (a_row + mf * 16) * PAD + kk + a_cb);
                    asm volatile("ldmatrix.sync.aligned.m8n8.x4.shared.b16 {%0,%1,%2,%3}, [%4];"
                        : "=r"(al[mf][0]), "=r"(al[mf][1]), "=r"(al[mf][2]), "=r"(al[mf][3])
                        : "r"(addr));
                }
#pragma unroll
                for (int mf = 0; mf < 4; mf++)
#pragma unroll
                    for (int nf = 0; nf < 8; nf++) MMA(al[mf], bh[nf]);
            }
            // hl: ah x bl
            {
                uint32_t bl[8][2];
#pragma unroll
                for (int nf2 = 0; nf2 < 4; nf2++) {
                    uint32_t addr = (uint32_t)__cvta_generic_to_shared(
                        Bl + (b_row + nf2 * 16) * PAD + kk + b_cb);
                    asm volatile("ldmatrix.sync.aligned.m8n8.x4.shared.b16 {%0,%1,%2,%3}, [%4];"
                        : "=r"(bl[nf2 * 2][0]), "=r"(bl[nf2 * 2][1]),
                          "=r"(bl[nf2 * 2 + 1][0]), "=r"(bl[nf2 * 2 + 1][1])
                        : "r"(addr));
                }
#pragma unroll
                for (int mf = 0; mf < 4; mf++)
#pragma unroll
                    for (int nf = 0; nf < 8; nf++) MMA(ah[mf], bl[nf]);
            }
#undef MMA
        }
    }

    // ---- epilogue ----
    if (b < 8) {
#pragma unroll
        for (int mf = 0; mf < 4; mf++) {
            int r1 = m0 + wm * 64 + mf * 16 + (lane >> 2);
            int r2 = r1 + 8;
#pragma unroll
            for (int nf = 0; nf < 8; nf++) {
                int col = wn * 64 + nf * 8 + (lane & 3) * 2;
                if (r1 < N_NODES)
                    *(__half2*)(g_xbh + (size_t)r1 * (NB * D) + b * D + col) =
                        __floats2half2_rn(acc[mf][nf][0], acc[mf][nf][1]);
                if (r2 < N_NODES)
                    *(__half2*)(g_xbh + (size_t)r2 * (NB * D) + b * D + col) =
                        __floats2half2_rn(acc[mf][nf][2], acc[mf][nf][3]);
            }
        }
        float ad[8];
#pragma unroll
        for (int j = 0; j < 8; j++) ad[j] = 0.f;
#pragma unroll
        for (int mf = 0; mf < 4; mf++)
#pragma unroll
            for (int nf = 0; nf < 8; nf++) {
                int col = wn * 64 + nf * 8 + (lane & 3) * 2;
                float a0 = atts[col], a1 = atts[col + 1];
                ad[mf * 2 + 0] = fmaf(a0, acc[mf][nf][0], fmaf(a1, acc[mf][nf][1], ad[mf * 2 + 0]));
                ad[mf * 2 + 1] = fmaf(a0, acc[mf][nf][2], fmaf(a1, acc[mf][nf][3], ad[mf * 2 + 1]));
            }
#pragma unroll
        for (int off = 1; off <= 2; off <<= 1)
#pragma unroll
            for (int j = 0; j < 8; j++) ad[j] += __shfl_xor_sync(0xffffffffu, ad[j], off);
        if ((lane & 3) == 0) {
            int rbase = m0 + wm * 64 + (lane >> 2);
#pragma unroll
            for (int mf = 0; mf < 4; mf++) {
                int g1 = rbase + mf * 16;
                if (g1 < N_NODES) atomicAdd(&g_attdot[(size_t)g1 * NB + b], ad[mf * 2 + 0]);
                if (g1 + 8 < N_NODES) atomicAdd(&g_attdot[(size_t)(g1 + 8) * NB + b], ad[mf * 2 + 1]);
            }
        }
    } else {
#pragma unroll
        for (int mf = 0; mf < 4; mf++) {
            int r1 = m0 + wm * 64 + mf * 16 + (lane >> 2);
            int r2 = r1 + 8;
#pragma unroll
            for (int nf = 0; nf < 8; nf++) {
                int col = wn * 64 + nf * 8 + (lane & 3) * 2;
                if (r1 < N_NODES)
                    *(float2*)(g_xloop + (size_t)r1 * D + col) =
                        make_float2(acc[mf][nf][0], acc[mf][nf][1]);
                if (r2 < N_NODES)
                    *(float2*)(g_xloop + (size_t)r2 * D + col) =
                        make_float2(acc[mf][nf][2], acc[mf][nf][3]);
            }
        }
    }
}

// ---------------- zero init (graph-replay safe) ----------------
__global__ void k_zero() {
    int idx = blockIdx.x * blockDim.x + threadIdx.x;
    int stride = gridDim.x * blockDim.x;
    for (int j = idx; j < N_NODES * D; j += stride) g_accum[j] = 0.f;
    for (int j = idx; j < N_NODES * NB; j += stride) g_attdot[j] = 0.f;
    for (int j = idx; j < N_NODES; j += stride) { g_denom[j] = 0.f; g_cnt[j] = 0; }
    if (idx < D) { g_colsum[idx] = 0.f; g_colsumsq[idx] = 0.f; }
}

// ---------------- CSR build ----------------
__global__ __launch_bounds__(256) void k_hist(const int* __restrict__ src) {
    int e = blockIdx.x * blockDim.x + threadIdx.x;
    if (e >= N_EDGES) return;
    atomicAdd(&g_cnt[src[e]], 1);
}

__global__ __launch_bounds__(1024) void k_scan() {
    __shared__ int ssum[1024];
    const int T = 1024, C = (N_NODES + T - 1) / T;   // 40
    int t = threadIdx.x;
    int lo = t * C, hi = min(lo + C, N_NODES);
    int s = 0;
    for (int i = lo; i < hi; i++) s += g_cnt[i];
    ssum[t] = s;
    __syncthreads();
    for (int off = 1; off < T; off <<= 1) {
        int u = (t >= off) ? ssum[t - off] : 0;
        __syncthreads();
        ssum[t] += u;
        __syncthreads();
    }
    int run = ssum[t] - s;   // exclusive prefix
    for (int i = lo; i < hi; i++) {
        g_off[i] = run;
        g_cur[i] = run;
        run += g_cnt[i];
    }
    if (t == 0) g_off[N_NODES] = N_EDGES;
}

__global__ __launch_bounds__(256) void k_scatter(const int* __restrict__ src,
                                                 const int* __restrict__ dst,
                                                 const int* __restrict__ rel) {
    int e = blockIdx.x * blockDim.x + threadIdx.x;
    if (e >= N_EDGES) return;
    int pos = atomicAdd(&g_cur[src[e]], 1);
    g_pk2[pos] = dst[e] * 32 + rel[e];
    g_eid2[pos] = e;
}

// ---------------- s[n,r] = sum_b coef[r,b] * attdot[n,b] ----------------
__global__ __launch_bounds__(256) void k_s2(const float* __restrict__ coef) {
    int t = blockIdx.x * blockDim.x + threadIdx.x;
    int node = t >> 5;
    int r = t & 31;
    if (node >= N_NODES) return;
    const float* ad = g_attdot + (size_t)node * NB;
    float s = 0.f;
#pragma unroll
    for (int b = 0; b < NB; b++) s = fmaf(coef[r * NB + b], ad[b], s);
    g_s[(size_t)node * R + r] = s;
}

// ---------------- edge pass 1 ----------------
__global__ __launch_bounds__(256) void k_edge1(const int* __restrict__ src,
                                               const int* __restrict__ dst,
                                               const int* __restrict__ rel) {
    int e = blockIdx.x * blockDim.x + threadIdx.x;
    if (e >= N_EDGES) return;
    int sN = src[e], dN = dst[e], rr = rel[e];
    float sc = g_s[(size_t)sN * R + rr] + g_s[(size_t)dN * R + rr];
    sc = (sc >= 0.f) ? sc : 0.01f * sc;
    float ez = expf(sc);
    g_ex[e] = ez;
    atomicAdd(&g_denom[dN], ez);
}

// ---------------- edge pass 2: CSR by src, warp per node ----------------
__global__ __launch_bounds__(256) void k_edge2(const float* __restrict__ coef) {
    int n = (blockIdx.x * blockDim.x + threadIdx.x) >> 5;
    int lane = threadIdx.x & 31;
    if (n >= N_NODES) return;
    int beg = g_off[n], end = g_off[n + 1];
    if (beg == end) return;
    // load this node's xb row once: per lane cols [lane*4, lane*4+3] for all 8 bases
    const uint2* xp = (const uint2*)(g_xbh + (size_t)n * (NB * D)) + lane;
    float f[NB][4];
#pragma unroll
    for (int b = 0; b < NB; b++) {
        uint2 u = xp[b * 32];
        float2 f0 = __half22float2(*(const __half2*)&u.x);
        float2 f1 = __half22float2(*(const __half2*)&u.y);
        f[b][0] = f0.x; f[b][1] = f0.y; f[b][2] = f1.x; f[b][3] = f1.y;
    }
    for (int j = beg; j < end; j++) {
        int pk = g_pk2[j];
        int e = g_eid2[j];
        int dN = pk >> 5, rr = pk & 31;
        float w = g_ex[e] / g_denom[dN];
        const float4* cp = (const float4*)(coef + rr * NB);
        float4 c0 = cp[0], c1 = cp[1];
        float4 acc;
        acc.x = c0.x * f[0][0]; acc.y = c0.x * f[0][1]; acc.z = c0.x * f[0][2]; acc.w = c0.x * f[0][3];
        acc.x = fmaf(c0.y, f[1][0], acc.x); acc.y = fmaf(c0.y, f[1][1], acc.y);
        acc.z = fmaf(c0.y, f[1][2], acc.z); acc.w = fmaf(c0.y, f[1][3], acc.w);
        acc.x = fmaf(c0.z, f[2][0], acc.x); acc.y = fmaf(c0.z, f[2][1], acc.y);
        acc.z = fmaf(c0.z, f[2][2], acc.z); acc.w = fmaf(c0.z, f[2][3], acc.w);
        acc.x = fmaf(c0.w, f[3][0], acc.x); acc.y = fmaf(c0.w, f[3][1], acc.y);
        acc.z = fmaf(c0.w, f[3][2], acc.z); acc.w = fmaf(c0.w, f[3][3], acc.w);
        acc.x = fmaf(c1.x, f[4][0], acc.x); acc.y = fmaf(c1.x, f[4][1], acc.y);
        acc.z = fmaf(c1.x, f[4][2], acc.z); acc.w = fmaf(c1.x, f[4][3], acc.w);
        acc.x = fmaf(c1.y, f[5][0], acc.x); acc.y = fmaf(c1.y, f[5][1], acc.y);
        acc.z = fmaf(c1.y, f[5][2], acc.z); acc.w = fmaf(c1.y, f[5][3], acc.w);
        acc.x = fmaf(c1.z, f[6][0], acc.x); acc.y = fmaf(c1.z, f[6][1], acc.y);
        acc.z = fmaf(c1.z, f[6][2], acc.z); acc.w = fmaf(c1.z, f[6][3], acc.w);
        acc.x = fmaf(c1.w, f[7][0], acc.x); acc.y = fmaf(c1.w, f[7][1], acc.y);
        acc.z = fmaf(c1.w, f[7][2], acc.z); acc.w = fmaf(c1.w, f[7][3], acc.w);
        acc.x *= w; acc.y *= w; acc.z *= w; acc.w *= w;
        atomicAdd((float4*)(g_accum + (size_t)dN * D + lane * 4), acc);
    }
}

// ---------------- ft + column stats ----------------
__global__ __launch_bounds__(128) void k_ft(const float* __restrict__ norm,
                                            const float* __restrict__ bias) {
    int o = threadIdx.x;
    float b = bias[o];
    float lsum = 0.f, lsq = 0.f;
    for (int n = blockIdx.x; n < N_NODES; n += gridDim.x) {
        float v = g_accum[(size_t)n * D + o] * norm[n] + b + g_xloop[(size_t)n * D + o];
        g_ft[(size_t)n * D + o] = v;
        lsum += v;
        lsq += v * v;
    }
    atomicAdd(&g_colsum[o], lsum);
    atomicAdd(&g_colsumsq[o], lsq);
}

// ---------------- BN finalize ----------------
__global__ void k_bn(const float* __restrict__ gamma, const float* __restrict__ beta) {
    int o = threadIdx.x;
    float mu = g_colsum[o] / (float)N_NODES;
    float var = g_colsumsq[o] / (float)N_NODES - mu * mu;
    float inv = rsqrtf(var + 1e-5f);
    float sc = gamma[o] * inv;
    g_scale[o] = sc;
    g_shift[o] = beta[o] - mu * sc;
}

// ---------------- output ----------------
__global__ __launch_bounds__(256) void k_out(float* __restrict__ out) {
    int i = blockIdx.x * blockDim.x + threadIdx.x;
    int total = N_NODES * D / 4;
    if (i >= total) return;
    float4 v = ((const float4*)g_ft)[i];
    int o = (i * 4) & (D - 1);
    float4 r;
    r.x = fmaxf(0.f, v.x * g_scale[o + 0] + g_shift[o + 0]);
    r.y = fmaxf(0.f, v.y * g_scale[o + 1] + g_shift[o + 1]);
    r.z = fmaxf(0.f, v.z * g_scale[o + 2] + g_shift[o + 2]);
    r.w = fmaxf(0.f, v.w * g_scale[o + 3] + g_shift[o + 3]);
    ((float4*)out)[i] = r;
}

extern "C" void kernel_launch(void* const* d_in, const int* in_sizes, int n_in,
                              void* d_out, int out_size) {
    const float* x       = (const float*)d_in[0];
    const float* norm    = (const float*)d_in[1];
    const int*   esrc    = (const int*)d_in[2];
    const int*   edst    = (const int*)d_in[3];
    const int*   erel    = (const int*)d_in[4];
    const float* w_loop  = (const float*)d_in[5];
    const float* w_bases = (const float*)d_in[6];
    const float* coef    = (const float*)d_in[7];
    const float* att     = (const float*)d_in[8];
    const float* bias    = (const float*)d_in[9];
    const float* gamma   = (const float*)d_in[10];
    const float* beta    = (const float*)d_in[11];
    float* out = (float*)d_out;

    k_zero<<<2048, 256>>>();
    k_convx<<<(N_NODES * D + 255) / 256, 256>>>(x);
    k_convw<<<(9 * D * D + 255) / 256, 256>>>(w_bases, w_loop);

    k_hist<<<(N_EDGES + 255) / 256, 256>>>(esrc);
    k_scan<<<1, 1024>>>();
    k_scatter<<<(N_EDGES + 255) / 256, 256>>>(esrc, edst, erel);

    dim3 gg((N_NODES + 127) / 128, 9);
    k_gemm_mma<<<gg, 128>>>(att);

    k_s2<<<(N_NODES * 32 + 255) / 256, 256>>>(coef);
    k_edge1<<<(N_EDGES + 255) / 256, 256>>>(esrc, edst, erel);
    k_edge2<<<(N_NODES * 32 + 255) / 256, 256>>>(coef);
    k_ft<<<512, 128>>>(norm, bias);
    k_bn<<<1, 128>>>(gamma, beta);
    k_out<<<(N_NODES * D / 4 + 255) / 256, 256>>>(out);
}

// round 6
// speedup vs baseline: 1.0464x; 1.0464x over previous
#include <cuda_runtime.h>
#include <cuda_bf16.h>
#include <cuda_fp16.h>
#include <cstdint>
#include <math.h>

#define N_NODES 40000
#define N_EDGES 640000
#define D 128
#define R 32
#define NB 8

// ---- scratch (static device globals; no runtime allocation) ----
__device__ __half g_xbh[(size_t)N_NODES * NB * D];  // 82 MB: bases 0-7, fp16
__device__ float g_xloop[(size_t)N_NODES * D];      // 20.5 MB: loop block fp32
__device__ float g_s[(size_t)N_NODES * R];          // 5.1 MB
__device__ float g_attdot[(size_t)N_NODES * NB];    // 1.28 MB
__device__ float g_ex[N_EDGES];
__device__ float g_denom[N_NODES];
__device__ float g_accum[(size_t)N_NODES * D];      // 20.5 MB
__device__ float g_ft[(size_t)N_NODES * D];         // 20.5 MB
__device__ float g_colsum[D];
__device__ float g_colsumsq[D];
__device__ float g_scale[D];
__device__ float g_shift[D];
__device__ __nv_bfloat16 g_xhi[(size_t)N_NODES * D];
__device__ __nv_bfloat16 g_xlo[(size_t)N_NODES * D];
__device__ __nv_bfloat16 g_wthi[9 * D * D];         // [b][n][k]  (W^T, k contiguous)
__device__ __nv_bfloat16 g_wtlo[9 * D * D];
// CSR by src
__device__ int g_cnt[N_NODES];
__device__ int g_cur[N_NODES];
__device__ int g_off[N_NODES + 1];
__device__ int g_pk2[N_EDGES];    // dst*32 + rel, CSR order
__device__ int g_eid2[N_EDGES];   // original edge id, CSR order
__device__ float g_w2[N_EDGES];   // normalized weight, CSR order

// ================= conversion kernels =================
__global__ void k_convx(const float* __restrict__ x) {
    int i = blockIdx.x * blockDim.x + threadIdx.x;
    if (i >= N_NODES * D) return;
    float v = x[i];
    __nv_bfloat16 h = __float2bfloat16(v);
    g_xhi[i] = h;
    g_xlo[i] = __float2bfloat16(v - __bfloat162float(h));
}

__global__ void k_convw(const float* __restrict__ w_bases, const float* __restrict__ w_loop) {
    int i = blockIdx.x * blockDim.x + threadIdx.x;
    if (i >= 9 * D * D) return;
    int b = i >> 14;
    int rem = i & 16383;
    int n = rem >> 7;
    int k = rem & 127;
    float v = (b < 8) ? w_bases[(b << 14) + k * D + n] : w_loop[k * D + n];
    __nv_bfloat16 h = __float2bfloat16(v);
    g_wthi[i] = h;
    g_wtlo[i] = __float2bfloat16(v - __bfloat162float(h));
}

// ================= mma.sync bf16 GEMM (round-4 proven config) =================
// Grid: (313 m-tiles, 9 bases). CTA = 256 thr = 8 warps (4 m x 2 n).

#define PAD 40

__global__ __launch_bounds__(256, 2) void k_gemm_mma(const float* __restrict__ att) {
    __shared__ __align__(16) __nv_bfloat16 Ah[128 * PAD];
    __shared__ __align__(16) __nv_bfloat16 Al[128 * PAD];
    __shared__ __align__(16) __nv_bfloat16 Bh[128 * PAD];
    __shared__ __align__(16) __nv_bfloat16 Bl[128 * PAD];
    __shared__ float atts[128];

    const int tid = threadIdx.x;
    const int lane = tid & 31;
    const int wid = tid >> 5;
    const int wm = wid & 3;       // 0..3 : 32-row strip
    const int wn = wid >> 2;      // 0..1 : 64-col strip
    const int m0 = blockIdx.x * 128;
    const int b = blockIdx.y;

    if (tid < 128) atts[tid] = att[tid];

    float acc[2][8][4];
#pragma unroll
    for (int mf = 0; mf < 2; mf++)
#pragma unroll
        for (int nf = 0; nf < 8; nf++)
#pragma unroll
            for (int r = 0; r < 4; r++) acc[mf][nf][r] = 0.f;

    const int a_row = wm * 32 + (lane & 15);
    const int a_cb = (lane >> 4) << 3;
    const int b_row = wn * 64 + (lane & 7) + ((lane >> 4) << 3);
    const int b_cb = (lane & 8);

    const __nv_bfloat16* Bgh = g_wthi + b * (D * D);
    const __nv_bfloat16* Bgl = g_wtlo + b * (D * D);

#pragma unroll 1
    for (int kc = 0; kc < 4; kc++) {
        const int k0 = kc * 32;
        __syncthreads();
#pragma unroll
        for (int l = 0; l < 2; l++) {
            int i = l * 256 + tid;          // 0..511 per tile
            int row = i >> 2;
            int c8 = (i & 3) * 8;
            int g = m0 + row;
            uint4 vh = make_uint4(0, 0, 0, 0), vl = make_uint4(0, 0, 0, 0);
            if (g < N_NODES) {
                vh = *(const uint4*)(g_xhi + (size_t)g * D + k0 + c8);
                vl = *(const uint4*)(g_xlo + (size_t)g * D + k0 + c8);
            }
            *(uint4*)(Ah + row * PAD + c8) = vh;
            *(uint4*)(Al + row * PAD + c8) = vl;
            *(uint4*)(Bh + row * PAD + c8) = *(const uint4*)(Bgh + row * D + k0 + c8);
            *(uint4*)(Bl + row * PAD + c8) = *(const uint4*)(Bgl + row * D + k0 + c8);
        }
        __syncthreads();
#pragma unroll
        for (int ks = 0; ks < 2; ks++) {
            const int kk = ks * 16;
            uint32_t ah[2][4], al[2][4];
#pragma unroll
            for (int mf = 0; mf < 2; mf++) {
                uint32_t addr = (uint32_t)__cvta_generic_to_shared(
                    Ah + (a_row + mf * 16) * PAD + kk + a_cb);
                asm volatile("ldmatrix.sync.aligned.m8n8.x4.shared.b16 {%0,%1,%2,%3}, [%4];"
                    : "=r"(ah[mf][0]), "=r"(ah[mf][1]), "=r"(ah[mf][2]), "=r"(ah[mf][3])
                    : "r"(addr));
                addr = (uint32_t)__cvta_generic_to_shared(
                    Al + (a_row + mf * 16) * PAD + kk + a_cb);
                asm volatile("ldmatrix.sync.aligned.m8n8.x4.shared.b16 {%0,%1,%2,%3}, [%4];"
                    : "=r"(al[mf][0]), "=r"(al[mf][1]), "=r"(al[mf][2]), "=r"(al[mf][3])
                    : "r"(addr));
            }
            uint32_t bh[8][2], bl[8][2];
#pragma unroll
            for (int nf2 = 0; nf2 < 4; nf2++) {
                uint32_t addr = (uint32_t)__cvta_generic_to_shared(
                    Bh + (b_row + nf2 * 16) * PAD + kk + b_cb);
                asm volatile("ldmatrix.sync.aligned.m8n8.x4.shared.b16 {%0,%1,%2,%3}, [%4];"
                    : "=r"(bh[nf2 * 2][0]), "=r"(bh[nf2 * 2][1]),
                      "=r"(bh[nf2 * 2 + 1][0]), "=r"(bh[nf2 * 2 + 1][1])
                    : "r"(addr));
                addr = (uint32_t)__cvta_generic_to_shared(
                    Bl + (b_row + nf2 * 16) * PAD + kk + b_cb);
                asm volatile("ldmatrix.sync.aligned.m8n8.x4.shared.b16 {%0,%1,%2,%3}, [%4];"
                    : "=r"(bl[nf2 * 2][0]), "=r"(bl[nf2 * 2][1]),
                      "=r"(bl[nf2 * 2 + 1][0]), "=r"(bl[nf2 * 2 + 1][1])
                    : "r"(addr));
            }
#define MMA(ar, br) \
    asm volatile("mma.sync.aligned.m16n8k16.row.col.f32.bf16.bf16.f32 " \
        "{%0,%1,%2,%3}, {%4,%5,%6,%7}, {%8,%9}, {%0,%1,%2,%3};" \
        : "+f"(acc[mf][nf][0]), "+f"(acc[mf][nf][1]), \
          "+f"(acc[mf][nf][2]), "+f"(acc[mf][nf][3]) \
        : "r"((ar)[0]), "r"((ar)[1]), "r"((ar)[2]), "r"((ar)[3]), \
          "r"((br)[0]), "r"((br)[1]))
#pragma unroll
            for (int mf = 0; mf < 2; mf++)
#pragma unroll
                for (int nf = 0; nf < 8; nf++) {
                    MMA(ah[mf], bh[nf]);
                    MMA(ah[mf], bl[nf]);
                    MMA(al[mf], bh[nf]);
                }
#undef MMA
        }
    }

    // ---- epilogue ----
    if (b < 8) {
#pragma unroll
        for (int mf = 0; mf < 2; mf++) {
            int r1 = m0 + wm * 32 + mf * 16 + (lane >> 2);
            int r2 = r1 + 8;
#pragma unroll
            for (int nf = 0; nf < 8; nf++) {
                int col = wn * 64 + nf * 8 + (lane & 3) * 2;
                if (r1 < N_NODES)
                    *(__half2*)(g_xbh + (size_t)r1 * (NB * D) + b * D + col) =
                        __floats2half2_rn(acc[mf][nf][0], acc[mf][nf][1]);
                if (r2 < N_NODES)
                    *(__half2*)(g_xbh + (size_t)r2 * (NB * D) + b * D + col) =
                        __floats2half2_rn(acc[mf][nf][2], acc[mf][nf][3]);
            }
        }
        float ad[4] = {0.f, 0.f, 0.f, 0.f};
#pragma unroll
        for (int mf = 0; mf < 2; mf++)
#pragma unroll
            for (int nf = 0; nf < 8; nf++) {
                int col = wn * 64 + nf * 8 + (lane & 3) * 2;
                float a0 = atts[col], a1 = atts[col + 1];
                ad[mf * 2 + 0] = fmaf(a0, acc[mf][nf][0], fmaf(a1, acc[mf][nf][1], ad[mf * 2 + 0]));
                ad[mf * 2 + 1] = fmaf(a0, acc[mf][nf][2], fmaf(a1, acc[mf][nf][3], ad[mf * 2 + 1]));
            }
#pragma unroll
        for (int off = 1; off <= 2; off <<= 1)
#pragma unroll
            for (int j = 0; j < 4; j++) ad[j] += __shfl_xor_sync(0xffffffffu, ad[j], off);
        if ((lane & 3) == 0) {
            int rbase = m0 + wm * 32 + (lane >> 2);
#pragma unroll
            for (int mf = 0; mf < 2; mf++) {
                int g1 = rbase + mf * 16;
                if (g1 < N_NODES) atomicAdd(&g_attdot[(size_t)g1 * NB + b], ad[mf * 2 + 0]);
                if (g1 + 8 < N_NODES) atomicAdd(&g_attdot[(size_t)(g1 + 8) * NB + b], ad[mf * 2 + 1]);
            }
        }
    } else {
#pragma unroll
        for (int mf = 0; mf < 2; mf++) {
            int r1 = m0 + wm * 32 + mf * 16 + (lane >> 2);
            int r2 = r1 + 8;
#pragma unroll
            for (int nf = 0; nf < 8; nf++) {
                int col = wn * 64 + nf * 8 + (lane & 3) * 2;
                if (r1 < N_NODES)
                    *(float2*)(g_xloop + (size_t)r1 * D + col) =
                        make_float2(acc[mf][nf][0], acc[mf][nf][1]);
                if (r2 < N_NODES)
                    *(float2*)(g_xloop + (size_t)r2 * D + col) =
                        make_float2(acc[mf][nf][2], acc[mf][nf][3]);
            }
        }
    }
}

// ---------------- zero init (graph-replay safe) ----------------
__global__ void k_zero() {
    int idx = blockIdx.x * blockDim.x + threadIdx.x;
    int stride = gridDim.x * blockDim.x;
    for (int j = idx; j < N_NODES * D; j += stride) g_accum[j] = 0.f;
    for (int j = idx; j < N_NODES * NB; j += stride) g_attdot[j] = 0.f;
    for (int j = idx; j < N_NODES; j += stride) { g_denom[j] = 0.f; g_cnt[j] = 0; }
    if (idx < D) { g_colsum[idx] = 0.f; g_colsumsq[idx] = 0.f; }
}

// ---------------- CSR build ----------------
__global__ __launch_bounds__(256) void k_hist(const int* __restrict__ src) {
    int e = blockIdx.x * blockDim.x + threadIdx.x;
    if (e >= N_EDGES) return;
    atomicAdd(&g_cnt[src[e]], 1);
}

__global__ __launch_bounds__(1024) void k_scan() {
    __shared__ int ssum[1024];
    const int T = 1024, C = (N_NODES + T - 1) / T;   // 40
    int t = threadIdx.x;
    int lo = t * C, hi = min(lo + C, N_NODES);
    int s = 0;
    for (int i = lo; i < hi; i++) s += g_cnt[i];
    ssum[t] = s;
    __syncthreads();
    for (int off = 1; off < T; off <<= 1) {
        int u = (t >= off) ? ssum[t - off] : 0;
        __syncthreads();
        ssum[t] += u;
        __syncthreads();
    }
    int run = ssum[t] - s;   // exclusive prefix
    for (int i = lo; i < hi; i++) {
        g_off[i] = run;
        g_cur[i] = run;
        run += g_cnt[i];
    }
    if (t == 0) g_off[N_NODES] = N_EDGES;
}

__global__ __launch_bounds__(256) void k_scatter(const int* __restrict__ src,
                                                 const int* __restrict__ dst,
                                                 const int* __restrict__ rel) {
    int e = blockIdx.x * blockDim.x + threadIdx.x;
    if (e >= N_EDGES) return;
    int pos = atomicAdd(&g_cur[src[e]], 1);
    g_pk2[pos] = dst[e] * 32 + rel[e];
    g_eid2[pos] = e;
}

// ---------------- s[n,r] = sum_b coef[r,b] * attdot[n,b] ----------------
__global__ __launch_bounds__(256) void k_s2(const float* __restrict__ coef) {
    int t = blockIdx.x * blockDim.x + threadIdx.x;
    int node = t >> 5;
    int r = t & 31;
    if (node >= N_NODES) return;
    const float* ad = g_attdot + (size_t)node * NB;
    float s = 0.f;
#pragma unroll
    for (int b = 0; b < NB; b++) s = fmaf(coef[r * NB + b], ad[b], s);
    g_s[(size_t)node * R + r] = s;
}

// ---------------- edge pass 1 ----------------
__global__ __launch_bounds__(256) void k_edge1(const int* __restrict__ src,
                                               const int* __restrict__ dst,
                                               const int* __restrict__ rel) {
    int e = blockIdx.x * blockDim.x + threadIdx.x;
    if (e >= N_EDGES) return;
    int sN = src[e], dN = dst[e], rr = rel[e];
    float sc = g_s[(size_t)sN * R + rr] + g_s[(size_t)dN * R + rr];
    sc = (sc >= 0.f) ? sc : 0.01f * sc;
    float ez = expf(sc);
    g_ex[e] = ez;
    atomicAdd(&g_denom[dN], ez);
}

// ---------------- normalized weights in CSR order ----------------
__global__ __launch_bounds__(256) void k_wnorm() {
    int j = blockIdx.x * blockDim.x + threadIdx.x;
    if (j >= N_EDGES) return;
    int e = g_eid2[j];
    int dN = g_pk2[j] >> 5;
    g_w2[j] = g_ex[e] / g_denom[dN];
}

// ---------------- edge pass 2: CSR by src, warp per node ----------------
__global__ __launch_bounds__(256) void k_edge2(const float* __restrict__ coef) {
    int n = (blockIdx.x * blockDim.x + threadIdx.x) >> 5;
    int lane = threadIdx.x & 31;
    if (n >= N_NODES) return;
    int beg = g_off[n], end = g_off[n + 1];
    if (beg == end) return;
    // load this node's xb row once: per lane cols [lane*4, lane*4+3] for all 8 bases
    const uint2* xp = (const uint2*)(g_xbh + (size_t)n * (NB * D)) + lane;
    float f[NB][4];
#pragma unroll
    for (int b = 0; b < NB; b++) {
        uint2 u = xp[b * 32];
        float2 f0 = __half22float2(*(const __half2*)&u.x);
        float2 f1 = __half22float2(*(const __half2*)&u.y);
        f[b][0] = f0.x; f[b][1] = f0.y; f[b][2] = f1.x; f[b][3] = f1.y;
    }
#pragma unroll 2
    for (int j = beg; j < end; j++) {
        int pk = g_pk2[j];
        float w = g_w2[j];
        int dN = pk >> 5, rr = pk & 31;
        const float4* cp = (const float4*)(coef + rr * NB);
        float4 c0 = cp[0], c1 = cp[1];
        float4 acc;
        acc.x = c0.x * f[0][0]; acc.y = c0.x * f[0][1]; acc.z = c0.x * f[0][2]; acc.w = c0.x * f[0][3];
        acc.x = fmaf(c0.y, f[1][0], acc.x); acc.y = fmaf(c0.y, f[1][1], acc.y);
        acc.z = fmaf(c0.y, f[1][2], acc.z); acc.w = fmaf(c0.y, f[1][3], acc.w);
        acc.x = fmaf(c0.z, f[2][0], acc.x); acc.y = fmaf(c0.z, f[2][1], acc.y);
        acc.z = fmaf(c0.z, f[2][2], acc.z); acc.w = fmaf(c0.z, f[2][3], acc.w);
        acc.x = fmaf(c0.w, f[3][0], acc.x); acc.y = fmaf(c0.w, f[3][1], acc.y);
        acc.z = fmaf(c0.w, f[3][2], acc.z); acc.w = fmaf(c0.w, f[3][3], acc.w);
        acc.x = fmaf(c1.x, f[4][0], acc.x); acc.y = fmaf(c1.x, f[4][1], acc.y);
        acc.z = fmaf(c1.x, f[4][2], acc.z); acc.w = fmaf(c1.x, f[4][3], acc.w);
        acc.x = fmaf(c1.y, f[5][0], acc.x); acc.y = fmaf(c1.y, f[5][1], acc.y);
        acc.z = fmaf(c1.y, f[5][2], acc.z); acc.w = fmaf(c1.y, f[5][3], acc.w);
        acc.x = fmaf(c1.z, f[6][0], acc.x); acc.y = fmaf(c1.z, f[6][1], acc.y);
        acc.z = fmaf(c1.z, f[6][2], acc.z); acc.w = fmaf(c1.z, f[6][3], acc.w);
        acc.x = fmaf(c1.w, f[7][0], acc.x); acc.y = fmaf(c1.w, f[7][1], acc.y);
        acc.z = fmaf(c1.w, f[7][2], acc.z); acc.w = fmaf(c1.w, f[7][3], acc.w);
        acc.x *= w; acc.y *= w; acc.z *= w; acc.w *= w;
        atomicAdd((float4*)(g_accum + (size_t)dN * D + lane * 4), acc);
    }
}

// ---------------- ft + column stats ----------------
__global__ __launch_bounds__(128) void k_ft(const float* __restrict__ norm,
                                            const float* __restrict__ bias) {
    int o = threadIdx.x;
    float b = bias[o];
    float lsum = 0.f, lsq = 0.f;
    for (int n = blockIdx.x; n < N_NODES; n += gridDim.x) {
        float v = g_accum[(size_t)n * D + o] * norm[n] + b + g_xloop[(size_t)n * D + o];
        g_ft[(size_t)n * D + o] = v;
        lsum += v;
        lsq += v * v;
    }
    atomicAdd(&g_colsum[o], lsum);
    atomicAdd(&g_colsumsq[o], lsq);
}

// ---------------- BN finalize ----------------
__global__ void k_bn(const float* __restrict__ gamma, const float* __restrict__ beta) {
    int o = threadIdx.x;
    float mu = g_colsum[o] / (float)N_NODES;
    float var = g_colsumsq[o] / (float)N_NODES - mu * mu;
    float inv = rsqrtf(var + 1e-5f);
    float sc = gamma[o] * inv;
    g_scale[o] = sc;
    g_shift[o] = beta[o] - mu * sc;
}

// ---------------- output ----------------
__global__ __launch_bounds__(256) void k_out(float* __restrict__ out) {
    int i = blockIdx.x * blockDim.x + threadIdx.x;
    int total = N_NODES * D / 4;
    if (i >= total) return;
    float4 v = ((const float4*)g_ft)[i];
    int o = (i * 4) & (D - 1);
    float4 r;
    r.x = fmaxf(0.f, v.x * g_scale[o + 0] + g_shift[o + 0]);
    r.y = fmaxf(0.f, v.y * g_scale[o + 1] + g_shift[o + 1]);
    r.z = fmaxf(0.f, v.z * g_scale[o + 2] + g_shift[o + 2]);
    r.w = fmaxf(0.f, v.w * g_scale[o + 3] + g_shift[o + 3]);
    ((float4*)out)[i] = r;
}

extern "C" void kernel_launch(void* const* d_in, const int* in_sizes, int n_in,
                              void* d_out, int out_size) {
    const float* x       = (const float*)d_in[0];
    const float* norm    = (const float*)d_in[1];
    const int*   esrc    = (const int*)d_in[2];
    const int*   edst    = (const int*)d_in[3];
    const int*   erel    = (const int*)d_in[4];
    const float* w_loop  = (const float*)d_in[5];
    const float* w_bases = (const float*)d_in[6];
    const float* coef    = (const float*)d_in[7];
    const float* att     = (const float*)d_in[8];
    const float* bias    = (const float*)d_in[9];
    const float* gamma   = (const float*)d_in[10];
    const float* beta    = (const float*)d_in[11];
    float* out = (float*)d_out;

    k_zero<<<2048, 256>>>();
    k_convx<<<(N_NODES * D + 255) / 256, 256>>>(x);
    k_convw<<<(9 * D * D + 255) / 256, 256>>>(w_bases, w_loop);

    k_hist<<<(N_EDGES + 255) / 256, 256>>>(esrc);
    k_scan<<<1, 1024>>>();
    k_scatter<<<(N_EDGES + 255) / 256, 256>>>(esrc, edst, erel);

    dim3 gg((N_NODES + 127) / 128, 9);
    k_gemm_mma<<<gg, 256>>>(att);

    k_s2<<<(N_NODES * 32 + 255) / 256, 256>>>(coef);
    k_edge1<<<(N_EDGES + 255) / 256, 256>>>(esrc, edst, erel);
    k_wnorm<<<(N_EDGES + 255) / 256, 256>>>();
    k_edge2<<<(N_NODES * 32 + 255) / 256, 256>>>(coef);
    k_ft<<<512, 128>>>(norm, bias);
    k_bn<<<1, 128>>>(gamma, beta);
    k_out<<<(N_NODES * D / 4 + 255) / 256, 256>>>(out);
}

// round 7
// speedup vs baseline: 1.1495x; 1.0986x over previous
#include <cuda_runtime.h>
#include <cuda_fp16.h>
#include <cstdint>
#include <math.h>

#define N_NODES 40000
#define N_EDGES 640000
#define D 128
#define R 32
#define NB 8

// ---- scratch (static device globals; no runtime allocation) ----
__device__ __half g_xbh[(size_t)N_NODES * NB * D];  // 82 MB: bases 0-7, fp16
__device__ float g_xloop[(size_t)N_NODES * D];      // 20.5 MB: loop block fp32
__device__ float g_s[(size_t)N_NODES * R];          // 5.1 MB
__device__ float g_attdot[(size_t)N_NODES * NB];    // 1.28 MB
__device__ float g_ex[N_EDGES];
__device__ float g_denom[N_NODES];
__device__ float g_accum[(size_t)N_NODES * D];      // 20.5 MB
__device__ float g_ft[(size_t)N_NODES * D];         // 20.5 MB
__device__ float g_colsum[D];
__device__ float g_colsumsq[D];
__device__ float g_scale[D];
__device__ float g_shift[D];
__device__ __half g_xh[(size_t)N_NODES * D];        // x hi (fp16)
__device__ __half g_xl[(size_t)N_NODES * D];        // x lo (fp16)
__device__ __half g_wth[9 * D * D];                 // [b][n][k]  (W^T hi, fp16)
// CSR by src
__device__ int g_cnt[N_NODES];
__device__ int g_cur[N_NODES];
__device__ int g_off[N_NODES + 1];
__device__ int g_pk2[N_EDGES];    // dst*32 + rel, CSR order
__device__ int g_eid2[N_EDGES];   // original edge id, CSR order
__device__ float g_w2[N_EDGES];   // normalized weight, CSR order

// ================= conversion kernels =================
__global__ void k_convx(const float* __restrict__ x) {
    int i = blockIdx.x * blockDim.x + threadIdx.x;
    if (i >= N_NODES * D) return;
    float v = x[i];
    __half h = __float2half_rn(v);
    g_xh[i] = h;
    g_xl[i] = __float2half_rn(v - __half2float(h));
}

__global__ void k_convw(const float* __restrict__ w_bases, const float* __restrict__ w_loop) {
    int i = blockIdx.x * blockDim.x + threadIdx.x;
    if (i >= 9 * D * D) return;
    int b = i >> 14;
    int rem = i & 16383;
    int n = rem >> 7;
    int k = rem & 127;
    float v = (b < 8) ? w_bases[(b << 14) + k * D + n] : w_loop[k * D + n];
    g_wth[i] = __float2half_rn(v);
}

// ================= mma.sync fp16 GEMM, 2-term compensated, cp.async pipelined =================
// Grid: (313 m-tiles, 9 bases). CTA = 256 thr = 8 warps (4 m x 2 n).
// Per k-chunk: Ah/Al/Bh tiles double-buffered via cp.async; 2 MMA groups (hh, lh).

#define PAD 40
#define TILE_H (128 * PAD)          // halfs per tile
#define TILE_B (TILE_H * 2)         // bytes per tile (10240)
#define SMEM_GEMM (512 + 6 * TILE_B)

__device__ __forceinline__ void cpa16(uint32_t dst, const void* src, int sz) {
    asm volatile("cp.async.ca.shared.global [%0], [%1], 16, %2;"
                 :: "r"(dst), "l"(src), "r"(sz));
}

__global__ __launch_bounds__(256, 2) void k_gemm_mma(const float* __restrict__ att) {
    extern __shared__ __align__(16) char dsm[];
    float* atts = (float*)dsm;
    __half* tiles = (__half*)(dsm + 512);

    const int tid = threadIdx.x;
    const int lane = tid & 31;
    const int wid = tid >> 5;
    const int wm = wid & 3;       // 0..3 : 32-row strip
    const int wn = wid >> 2;      // 0..1 : 64-col strip
    const int m0 = blockIdx.x * 128;
    const int b = blockIdx.y;

    if (tid < 128) atts[tid] = att[tid];

    float acc[2][8][4];
#pragma unroll
    for (int mf = 0; mf < 2; mf++)
#pragma unroll
        for (int nf = 0; nf < 8; nf++)
#pragma unroll
            for (int r = 0; r < 4; r++) acc[mf][nf][r] = 0.f;

    const int a_row = wm * 32 + (lane & 15);
    const int a_cb = (lane >> 4) << 3;
    const int b_row = wn * 64 + (lane & 7) + ((lane >> 4) << 3);
    const int b_cb = (lane & 8);

    const __half* Bg = g_wth + b * (D * D);

    // fill slot indices (constant across kc)
    const int fi_row[2] = { (0 * 256 + tid) >> 2, (1 * 256 + tid) >> 2 };
    const int fi_c8[2]  = { ((0 * 256 + tid) & 3) * 8, ((1 * 256 + tid) & 3) * 8 };

#define ISSUE_FILL(kc, s) do {                                                    \
    const int _k0 = (kc) * 32;                                                    \
    __half* _Ah = tiles + (s) * 3 * TILE_H;                                       \
    __half* _Al = _Ah + TILE_H;                                                   \
    __half* _Bh = _Ah + 2 * TILE_H;                                               \
    _Pragma("unroll")                                                             \
    for (int _l = 0; _l < 2; _l++) {                                              \
        int _row = fi_row[_l], _c8 = fi_c8[_l];                                   \
        int _g = m0 + _row;                                                       \
        bool _ok = _g < N_NODES;                                                  \
        int _gc = _ok ? _g : 0;                                                   \
        int _sz = _ok ? 16 : 0;                                                   \
        cpa16((uint32_t)__cvta_generic_to_shared(_Ah + _row * PAD + _c8),         \
              g_xh + (size_t)_gc * D + _k0 + _c8, _sz);                           \
        cpa16((uint32_t)__cvta_generic_to_shared(_Al + _row * PAD + _c8),         \
              g_xl + (size_t)_gc * D + _k0 + _c8, _sz);                           \
        cpa16((uint32_t)__cvta_generic_to_shared(_Bh + _row * PAD + _c8),         \
              Bg + _row * D + _k0 + _c8, 16);                                     \
    }                                                                             \
    asm volatile("cp.async.commit_group;" ::: "memory");                          \
} while (0)

    ISSUE_FILL(0, 0);

#pragma unroll 1
    for (int kc = 0; kc < 4; kc++) {
        const int s = kc & 1;
        if (kc < 3) {
            ISSUE_FILL(kc + 1, s ^ 1);
            asm volatile("cp.async.wait_group 1;" ::: "memory");
        } else {
            asm volatile("cp.async.wait_group 0;" ::: "memory");
        }
        __syncthreads();

        const __half* Ah = tiles + s * 3 * TILE_H;
        const __half* Al = Ah + TILE_H;
        const __half* Bh = Ah + 2 * TILE_H;

#pragma unroll
        for (int ks = 0; ks < 2; ks++) {
            const int kk = ks * 16;
            uint32_t ah[2][4], al[2][4], bh[8][2];
#pragma unroll
            for (int mf = 0; mf < 2; mf++) {
                uint32_t addr = (uint32_t)__cvta_generic_to_shared(
                    Ah + (a_row + mf * 16) * PAD + kk + a_cb);
                asm volatile("ldmatrix.sync.aligned.m8n8.x4.shared.b16 {%0,%1,%2,%3}, [%4];"
                    : "=r"(ah[mf][0]), "=r"(ah[mf][1]), "=r"(ah[mf][2]), "=r"(ah[mf][3])
                    : "r"(addr));
                addr = (uint32_t)__cvta_generic_to_shared(
                    Al + (a_row + mf * 16) * PAD + kk + a_cb);
                asm volatile("ldmatrix.sync.aligned.m8n8.x4.shared.b16 {%0,%1,%2,%3}, [%4];"
                    : "=r"(al[mf][0]), "=r"(al[mf][1]), "=r"(al[mf][2]), "=r"(al[mf][3])
                    : "r"(addr));
            }
#pragma unroll
            for (int nf2 = 0; nf2 < 4; nf2++) {
                uint32_t addr = (uint32_t)__cvta_generic_to_shared(
                    Bh + (b_row + nf2 * 16) * PAD + kk + b_cb);
                asm volatile("ldmatrix.sync.aligned.m8n8.x4.shared.b16 {%0,%1,%2,%3}, [%4];"
                    : "=r"(bh[nf2 * 2][0]), "=r"(bh[nf2 * 2][1]),
                      "=r"(bh[nf2 * 2 + 1][0]), "=r"(bh[nf2 * 2 + 1][1])
                    : "r"(addr));
            }
#define MMA(ar, br) \
    asm volatile("mma.sync.aligned.m16n8k16.row.col.f32.f16.f16.f32 " \
        "{%0,%1,%2,%3}, {%4,%5,%6,%7}, {%8,%9}, {%0,%1,%2,%3};" \
        : "+f"(acc[mf][nf][0]), "+f"(acc[mf][nf][1]), \
          "+f"(acc[mf][nf][2]), "+f"(acc[mf][nf][3]) \
        : "r"((ar)[0]), "r"((ar)[1]), "r"((ar)[2]), "r"((ar)[3]), \
          "r"((br)[0]), "r"((br)[1]))
#pragma unroll
            for (int mf = 0; mf < 2; mf++)
#pragma unroll
                for (int nf = 0; nf < 8; nf++) {
                    MMA(ah[mf], bh[nf]);
                    MMA(al[mf], bh[nf]);
                }
#undef MMA
        }
        __syncthreads();
    }

    // ---- epilogue ----
    if (b < 8) {
#pragma unroll
        for (int mf = 0; mf < 2; mf++) {
            int r1 = m0 + wm * 32 + mf * 16 + (lane >> 2);
            int r2 = r1 + 8;
#pragma unroll
            for (int nf = 0; nf < 8; nf++) {
                int col = wn * 64 + nf * 8 + (lane & 3) * 2;
                if (r1 < N_NODES)
                    *(__half2*)(g_xbh + (size_t)r1 * (NB * D) + b * D + col) =
                        __floats2half2_rn(acc[mf][nf][0], acc[mf][nf][1]);
                if (r2 < N_NODES)
                    *(__half2*)(g_xbh + (size_t)r2 * (NB * D) + b * D + col) =
                        __floats2half2_rn(acc[mf][nf][2], acc[mf][nf][3]);
            }
        }
        float ad[4] = {0.f, 0.f, 0.f, 0.f};
#pragma unroll
        for (int mf = 0; mf < 2; mf++)
#pragma unroll
            for (int nf = 0; nf < 8; nf++) {
                int col = wn * 64 + nf * 8 + (lane & 3) * 2;
                float a0 = atts[col], a1 = atts[col + 1];
                ad[mf * 2 + 0] = fmaf(a0, acc[mf][nf][0], fmaf(a1, acc[mf][nf][1], ad[mf * 2 + 0]));
                ad[mf * 2 + 1] = fmaf(a0, acc[mf][nf][2], fmaf(a1, acc[mf][nf][3], ad[mf * 2 + 1]));
            }
#pragma unroll
        for (int off = 1; off <= 2; off <<= 1)
#pragma unroll
            for (int j = 0; j < 4; j++) ad[j] += __shfl_xor_sync(0xffffffffu, ad[j], off);
        if ((lane & 3) == 0) {
            int rbase = m0 + wm * 32 + (lane >> 2);
#pragma unroll
            for (int mf = 0; mf < 2; mf++) {
                int g1 = rbase + mf * 16;
                if (g1 < N_NODES) atomicAdd(&g_attdot[(size_t)g1 * NB + b], ad[mf * 2 + 0]);
                if (g1 + 8 < N_NODES) atomicAdd(&g_attdot[(size_t)(g1 + 8) * NB + b], ad[mf * 2 + 1]);
            }
        }
    } else {
#pragma unroll
        for (int mf = 0; mf < 2; mf++) {
            int r1 = m0 + wm * 32 + mf * 16 + (lane >> 2);
            int r2 = r1 + 8;
#pragma unroll
            for (int nf = 0; nf < 8; nf++) {
                int col = wn * 64 + nf * 8 + (lane & 3) * 2;
                if (r1 < N_NODES)
                    *(float2*)(g_xloop + (size_t)r1 * D + col) =
                        make_float2(acc[mf][nf][0], acc[mf][nf][1]);
                if (r2 < N_NODES)
                    *(float2*)(g_xloop + (size_t)r2 * D + col) =
                        make_float2(acc[mf][nf][2], acc[mf][nf][3]);
            }
        }
    }
}

// ---------------- zero init (graph-replay safe) ----------------
__global__ void k_zero() {
    int idx = blockIdx.x * blockDim.x + threadIdx.x;
    int stride = gridDim.x * blockDim.x;
    for (int j = idx; j < N_NODES * D; j += stride) g_accum[j] = 0.f;
    for (int j = idx; j < N_NODES * NB; j += stride) g_attdot[j] = 0.f;
    for (int j = idx; j < N_NODES; j += stride) { g_denom[j] = 0.f; g_cnt[j] = 0; }
    if (idx < D) { g_colsum[idx] = 0.f; g_colsumsq[idx] = 0.f; }
}

// ---------------- CSR build ----------------
__global__ __launch_bounds__(256) void k_hist(const int* __restrict__ src) {
    int e = blockIdx.x * blockDim.x + threadIdx.x;
    if (e >= N_EDGES) return;
    atomicAdd(&g_cnt[src[e]], 1);
}

__global__ __launch_bounds__(1024) void k_scan() {
    __shared__ int ssum[1024];
    const int T = 1024, C = (N_NODES + T - 1) / T;   // 40
    int t = threadIdx.x;
    int lo = t * C, hi = min(lo + C, N_NODES);
    int s = 0;
    for (int i = lo; i < hi; i++) s += g_cnt[i];
    ssum[t] = s;
    __syncthreads();
    for (int off = 1; off < T; off <<= 1) {
        int u = (t >= off) ? ssum[t - off] : 0;
        __syncthreads();
        ssum[t] += u;
        __syncthreads();
    }
    int run = ssum[t] - s;   // exclusive prefix
    for (int i = lo; i < hi; i++) {
        g_off[i] = run;
        g_cur[i] = run;
        run += g_cnt[i];
    }
    if (t == 0) g_off[N_NODES] = N_EDGES;
}

__global__ __launch_bounds__(256) void k_scatter(const int* __restrict__ src,
                                                 const int* __restrict__ dst,
                                                 const int* __restrict__ rel) {
    int e = blockIdx.x * blockDim.x + threadIdx.x;
    if (e >= N_EDGES) return;
    int pos = atomicAdd(&g_cur[src[e]], 1);
    g_pk2[pos] = dst[e] * 32 + rel[e];
    g_eid2[pos] = e;
}

// ---------------- s[n,r] = sum_b coef[r,b] * attdot[n,b] ----------------
__global__ __launch_bounds__(256) void k_s2(const float* __restrict__ coef) {
    int t = blockIdx.x * blockDim.x + threadIdx.x;
    int node = t >> 5;
    int r = t & 31;
    if (node >= N_NODES) return;
    const float* ad = g_attdot + (size_t)node * NB;
    float s = 0.f;
#pragma unroll
    for (int b = 0; b < NB; b++) s = fmaf(coef[r * NB + b], ad[b], s);
    g_s[(size_t)node * R + r] = s;
}

// ---------------- edge pass 1 ----------------
__global__ __launch_bounds__(256) void k_edge1(const int* __restrict__ src,
                                               const int* __restrict__ dst,
                                               const int* __restrict__ rel) {
    int e = blockIdx.x * blockDim.x + threadIdx.x;
    if (e >= N_EDGES) return;
    int sN = src[e], dN = dst[e], rr = rel[e];
    float sc = g_s[(size_t)sN * R + rr] + g_s[(size_t)dN * R + rr];
    sc = (sc >= 0.f) ? sc : 0.01f * sc;
    float ez = expf(sc);
    g_ex[e] = ez;
    atomicAdd(&g_denom[dN], ez);
}

// ---------------- normalized weights in CSR order ----------------
__global__ __launch_bounds__(256) void k_wnorm() {
    int j = blockIdx.x * blockDim.x + threadIdx.x;
    if (j >= N_EDGES) return;
    int e = g_eid2[j];
    int dN = g_pk2[j] >> 5;
    g_w2[j] = g_ex[e] / g_denom[dN];
}

// ---------------- edge pass 2: CSR by src, warp per node ----------------
__global__ __launch_bounds__(256) void k_edge2(const float* __restrict__ coef) {
    int n = (blockIdx.x * blockDim.x + threadIdx.x) >> 5;
    int lane = threadIdx.x & 31;
    if (n >= N_NODES) return;
    int beg = g_off[n], end = g_off[n + 1];
    if (beg == end) return;
    const uint2* xp = (const uint2*)(g_xbh + (size_t)n * (NB * D)) + lane;
    float f[NB][4];
#pragma unroll
    for (int b = 0; b < NB; b++) {
        uint2 u = xp[b * 32];
        float2 f0 = __half22float2(*(const __half2*)&u.x);
        float2 f1 = __half22float2(*(const __half2*)&u.y);
        f[b][0] = f0.x; f[b][1] = f0.y; f[b][2] = f1.x; f[b][3] = f1.y;
    }
#pragma unroll 2
    for (int j = beg; j < end; j++) {
        int pk = g_pk2[j];
        float w = g_w2[j];
        int dN = pk >> 5, rr = pk & 31;
        const float4* cp = (const float4*)(coef + rr * NB);
        float4 c0 = cp[0], c1 = cp[1];
        float4 acc;
        acc.x = c0.x * f[0][0]; acc.y = c0.x * f[0][1]; acc.z = c0.x * f[0][2]; acc.w = c0.x * f[0][3];
        acc.x = fmaf(c0.y, f[1][0], acc.x); acc.y = fmaf(c0.y, f[1][1], acc.y);
        acc.z = fmaf(c0.y, f[1][2], acc.z); acc.w = fmaf(c0.y, f[1][3], acc.w);
        acc.x = fmaf(c0.z, f[2][0], acc.x); acc.y = fmaf(c0.z, f[2][1], acc.y);
        acc.z = fmaf(c0.z, f[2][2], acc.z); acc.w = fmaf(c0.z, f[2][3], acc.w);
        acc.x = fmaf(c0.w, f[3][0], acc.x); acc.y = fmaf(c0.w, f[3][1], acc.y);
        acc.z = fmaf(c0.w, f[3][2], acc.z); acc.w = fmaf(c0.w, f[3][3], acc.w);
        acc.x = fmaf(c1.x, f[4][0], acc.x); acc.y = fmaf(c1.x, f[4][1], acc.y);
        acc.z = fmaf(c1.x, f[4][2], acc.z); acc.w = fmaf(c1.x, f[4][3], acc.w);
        acc.x = fmaf(c1.y, f[5][0], acc.x); acc.y = fmaf(c1.y, f[5][1], acc.y);
        acc.z = fmaf(c1.y, f[5][2], acc.z); acc.w = fmaf(c1.y, f[5][3], acc.w);
        acc.x = fmaf(c1.z, f[6][0], acc.x); acc.y = fmaf(c1.z, f[6][1], acc.y);
        acc.z = fmaf(c1.z, f[6][2], acc.z); acc.w = fmaf(c1.z, f[6][3], acc.w);
        acc.x = fmaf(c1.w, f[7][0], acc.x); acc.y = fmaf(c1.w, f[7][1], acc.y);
        acc.z = fmaf(c1.w, f[7][2], acc.z); acc.w = fmaf(c1.w, f[7][3], acc.w);
        acc.x *= w; acc.y *= w; acc.z *= w; acc.w *= w;
        atomicAdd((float4*)(g_accum + (size_t)dN * D + lane * 4), acc);
    }
}

// ---------------- ft + column stats ----------------
__global__ __launch_bounds__(128) void k_ft(const float* __restrict__ norm,
                                            const float* __restrict__ bias) {
    int o = threadIdx.x;
    float b = bias[o];
    float lsum = 0.f, lsq = 0.f;
    for (int n = blockIdx.x; n < N_NODES; n += gridDim.x) {
        float v = g_accum[(size_t)n * D + o] * norm[n] + b + g_xloop[(size_t)n * D + o];
        g_ft[(size_t)n * D + o] = v;
        lsum += v;
        lsq += v * v;
    }
    atomicAdd(&g_colsum[o], lsum);
    atomicAdd(&g_colsumsq[o], lsq);
}

// ---------------- BN finalize ----------------
__global__ void k_bn(const float* __restrict__ gamma, const float* __restrict__ beta) {
    int o = threadIdx.x;
    float mu = g_colsum[o] / (float)N_NODES;
    float var = g_colsumsq[o] / (float)N_NODES - mu * mu;
    float inv = rsqrtf(var + 1e-5f);
    float sc = gamma[o] * inv;
    g_scale[o] = sc;
    g_shift[o] = beta[o] - mu * sc;
}

// ---------------- output ----------------
__global__ __launch_bounds__(256) void k_out(float* __restrict__ out) {
    int i = blockIdx.x * blockDim.x + threadIdx.x;
    int total = N_NODES * D / 4;
    if (i >= total) return;
    float4 v = ((const float4*)g_ft)[i];
    int o = (i * 4) & (D - 1);
    float4 r;
    r.x = fmaxf(0.f, v.x * g_scale[o + 0] + g_shift[o + 0]);
    r.y = fmaxf(0.f, v.y * g_scale[o + 1] + g_shift[o + 1]);
    r.z = fmaxf(0.f, v.z * g_scale[o + 2] + g_shift[o + 2]);
    r.w = fmaxf(0.f, v.w * g_scale[o + 3] + g_shift[o + 3]);
    ((float4*)out)[i] = r;
}

extern "C" void kernel_launch(void* const* d_in, const int* in_sizes, int n_in,
                              void* d_out, int out_size) {
    const float* x       = (const float*)d_in[0];
    const float* norm    = (const float*)d_in[1];
    const int*   esrc    = (const int*)d_in[2];
    const int*   edst    = (const int*)d_in[3];
    const int*   erel    = (const int*)d_in[4];
    const float* w_loop  = (const float*)d_in[5];
    const float* w_bases = (const float*)d_in[6];
    const float* coef    = (const float*)d_in[7];
    const float* att     = (const float*)d_in[8];
    const float* bias    = (const float*)d_in[9];
    const float* gamma   = (const float*)d_in[10];
    const float* beta    = (const float*)d_in[11];
    float* out = (float*)d_out;

    cudaFuncSetAttribute(k_gemm_mma, cudaFuncAttributeMaxDynamicSharedMemorySize, SMEM_GEMM);

    k_zero<<<2048, 256>>>();
    k_convx<<<(N_NODES * D + 255) / 256, 256>>>(x);
    k_convw<<<(9 * D * D + 255) / 256, 256>>>(w_bases, w_loop);

    k_hist<<<(N_EDGES + 255) / 256, 256>>>(esrc);
    k_scan<<<1, 1024>>>();
    k_scatter<<<(N_EDGES + 255) / 256, 256>>>(esrc, edst, erel);

    dim3 gg((N_NODES + 127) / 128, 9);
    k_gemm_mma<<<gg, 256, SMEM_GEMM>>>(att);

    k_s2<<<(N_NODES * 32 + 255) / 256, 256>>>(coef);
    k_edge1<<<(N_EDGES + 255) / 256, 256>>>(esrc, edst, erel);
    k_wnorm<<<(N_EDGES + 255) / 256, 256>>>();
    k_edge2<<<(N_NODES * 32 + 255) / 256, 256>>>(coef);
    k_ft<<<512, 128>>>(norm, bias);
    k_bn<<<1, 128>>>(gamma, beta);
    k_out<<<(N_NODES * D / 4 + 255) / 256, 256>>>(out);
}

// round 8
// speedup vs baseline: 1.1872x; 1.0328x over previous
#include <cuda_runtime.h>
#include <cuda_fp16.h>
#include <cstdint>
#include <math.h>

#define N_NODES 40000
#define N_EDGES 640000
#define D 128
#define R 32
#define NB 8

// ---- scratch (static device globals; no runtime allocation) ----
__device__ __half g_xbh[(size_t)N_NODES * NB * D];  // 82 MB: bases 0-7, fp16
__device__ float g_xloop[(size_t)N_NODES * D];      // 20.5 MB: loop block fp32
__device__ float g_s[(size_t)N_NODES * R];          // 5.1 MB
__device__ float g_attdot[(size_t)N_NODES * NB];    // 1.28 MB
__device__ float g_ex[N_EDGES];
__device__ float g_denom[N_NODES];
__device__ float g_accum[(size_t)N_NODES * D];      // 20.5 MB
__device__ float g_colsum[D];
__device__ float g_colsumsq[D];
__device__ float g_scale[D];
__device__ float g_shift[D];
__device__ __half g_xh[(size_t)N_NODES * D];        // x hi (fp16)
__device__ __half g_xl[(size_t)N_NODES * D];        // x lo (fp16)
__device__ __half g_wth[9 * D * D];                 // [b][n][k]  (W^T, fp16)
// CSR by src
__device__ int g_cnt[N_NODES];
__device__ int g_cur[N_NODES];
__device__ int g_off[N_NODES + 1];
__device__ int g_pk2[N_EDGES];    // dst*32 + rel, CSR order
__device__ int g_eid2[N_EDGES];   // original edge id, CSR order
__device__ float g_w2[N_EDGES];   // normalized weight, CSR order

// ================= fused prep: zero + convert x + convert W =================
__global__ __launch_bounds__(256) void k_prep(const float* __restrict__ x,
                                              const float* __restrict__ w_bases,
                                              const float* __restrict__ w_loop) {
    int idx0 = blockIdx.x * blockDim.x + threadIdx.x;
    int stride = gridDim.x * blockDim.x;
    for (int i = idx0; i < N_NODES * D; i += stride) {
        g_accum[i] = 0.f;
        float v = x[i];
        __half h = __float2half_rn(v);
        g_xh[i] = h;
        g_xl[i] = __float2half_rn(v - __half2float(h));
    }
    for (int i = idx0; i < 9 * D * D; i += stride) {
        int b = i >> 14;
        int rem = i & 16383;
        int n = rem >> 7;
        int k = rem & 127;
        float v = (b < 8) ? w_bases[(b << 14) + k * D + n] : w_loop[k * D + n];
        g_wth[i] = __float2half_rn(v);
    }
    for (int i = idx0; i < N_NODES * NB; i += stride) g_attdot[i] = 0.f;
    for (int i = idx0; i < N_NODES; i += stride) { g_denom[i] = 0.f; g_cnt[i] = 0; }
    if (idx0 < D) { g_colsum[idx0] = 0.f; g_colsumsq[idx0] = 0.f; }
}

// ================= mma.sync fp16 GEMM, A-resident, 3 bases per CTA =================
// Grid: (313 m-tiles, 3 base-groups). CTA = 256 thr = 8 warps (4 m x 2 n).
// A hi/lo (all 4 k-chunks) resident in smem; B tile double-buffered per (basis, kc).

#define PAD 40
#define TILE_H (128 * PAD)          // halfs per tile
#define TILE_B (TILE_H * 2)         // bytes per tile (10240)
#define SMEM_GEMM (512 + 10 * TILE_B)   // 8 A tiles + 2 B buffers + atts

__device__ __forceinline__ void cpa16(uint32_t dst, const void* src, int sz) {
    asm volatile("cp.async.ca.shared.global [%0], [%1], 16, %2;"
                 :: "r"(dst), "l"(src), "r"(sz));
}

__global__ __launch_bounds__(256, 2) void k_gemm_mma(const float* __restrict__ att) {
    extern __shared__ __align__(16) char dsm[];
    float* atts = (float*)dsm;
    __half* tiles = (__half*)(dsm + 512);

    const int tid = threadIdx.x;
    const int lane = tid & 31;
    const int wid = tid >> 5;
    const int wm = wid & 3;       // 0..3 : 32-row strip
    const int wn = wid >> 2;      // 0..1 : 64-col strip
    const int m0 = blockIdx.x * 128;
    const int bgrp = blockIdx.y;  // 0..2 -> bases bgrp*3 .. bgrp*3+2

    if (tid < 128) atts[tid] = att[tid];

    const int fi_row[2] = { (0 * 256 + tid) >> 2, (1 * 256 + tid) >> 2 };
    const int fi_c8[2]  = { ((0 * 256 + tid) & 3) * 8, ((1 * 256 + tid) & 3) * 8 };

    // ---- load all A tiles (4 kc x hi/lo) ----
#pragma unroll
    for (int kc = 0; kc < 4; kc++) {
        __half* Ahi = tiles + kc * TILE_H;
        __half* Alo = tiles + (4 + kc) * TILE_H;
#pragma unroll
        for (int l = 0; l < 2; l++) {
            int row = fi_row[l], c8 = fi_c8[l];
            int g = m0 + row;
            bool ok = g < N_NODES;
            int gc = ok ? g : 0;
            int sz = ok ? 16 : 0;
            cpa16((uint32_t)__cvta_generic_to_shared(Ahi + row * PAD + c8),
                  g_xh + (size_t)gc * D + kc * 32 + c8, sz);
            cpa16((uint32_t)__cvta_generic_to_shared(Alo + row * PAD + c8),
                  g_xl + (size_t)gc * D + kc * 32 + c8, sz);
        }
    }
    asm volatile("cp.async.commit_group;" ::: "memory");

#define ISSUE_B(jj, s) do {                                                       \
    const int _b = bgrp * 3 + ((jj) >> 2);                                        \
    const int _k0 = ((jj) & 3) * 32;                                              \
    const __half* _Bg = g_wth + _b * (D * D);                                     \
    __half* _Bs = tiles + (8 + (s)) * TILE_H;                                     \
    _Pragma("unroll")                                                             \
    for (int _l = 0; _l < 2; _l++) {                                              \
        int _row = fi_row[_l], _c8 = fi_c8[_l];                                   \
        cpa16((uint32_t)__cvta_generic_to_shared(_Bs + _row * PAD + _c8),         \
              _Bg + _row * D + _k0 + _c8, 16);                                    \
    }                                                                             \
    asm volatile("cp.async.commit_group;" ::: "memory");                          \
} while (0)

    ISSUE_B(0, 0);

    const int a_row = wm * 32 + (lane & 15);
    const int a_cb = (lane >> 4) << 3;
    const int b_row = wn * 64 + (lane & 7) + ((lane >> 4) << 3);
    const int b_cb = (lane & 8);

    float acc[2][8][4];

#pragma unroll 1
    for (int j = 0; j < 12; j++) {
        const int kc = j & 3;
        const int s = j & 1;
        __syncthreads();               // prior consumption of buffer s^1 finished
        if (j < 11) {
            ISSUE_B(j + 1, s ^ 1);
            asm volatile("cp.async.wait_group 1;" ::: "memory");
        } else {
            asm volatile("cp.async.wait_group 0;" ::: "memory");
        }
        __syncthreads();               // fills visible to all warps

        if (kc == 0) {
#pragma unroll
            for (int mf = 0; mf < 2; mf++)
#pragma unroll
                for (int nf = 0; nf < 8; nf++)
#pragma unroll
                    for (int r = 0; r < 4; r++) acc[mf][nf][r] = 0.f;
        }

        const __half* Ah = tiles + kc * TILE_H;
        const __half* Al = tiles + (4 + kc) * TILE_H;
        const __half* Bh = tiles + (8 + s) * TILE_H;

#pragma unroll
        for (int ks = 0; ks < 2; ks++) {
            const int kk = ks * 16;
            uint32_t ah[2][4], al[2][4], bh[8][2];
#pragma unroll
            for (int mf = 0; mf < 2; mf++) {
                uint32_t addr = (uint32_t)__cvta_generic_to_shared(
                    Ah + (a_row + mf * 16) * PAD + kk + a_cb);
                asm volatile("ldmatrix.sync.aligned.m8n8.x4.shared.b16 {%0,%1,%2,%3}, [%4];"
                    : "=r"(ah[mf][0]), "=r"(ah[mf][1]), "=r"(ah[mf][2]), "=r"(ah[mf][3])
                    : "r"(addr));
                addr = (uint32_t)__cvta_generic_to_shared(
                    Al + (a_row + mf * 16) * PAD + kk + a_cb);
                asm volatile("ldmatrix.sync.aligned.m8n8.x4.shared.b16 {%0,%1,%2,%3}, [%4];"
                    : "=r"(al[mf][0]), "=r"(al[mf][1]), "=r"(al[mf][2]), "=r"(al[mf][3])
                    : "r"(addr));
            }
#pragma unroll
            for (int nf2 = 0; nf2 < 4; nf2++) {
                uint32_t addr = (uint32_t)__cvta_generic_to_shared(
                    Bh + (b_row + nf2 * 16) * PAD + kk + b_cb);
                asm volatile("ldmatrix.sync.aligned.m8n8.x4.shared.b16 {%0,%1,%2,%3}, [%4];"
                    : "=r"(bh[nf2 * 2][0]), "=r"(bh[nf2 * 2][1]),
                      "=r"(bh[nf2 * 2 + 1][0]), "=r"(bh[nf2 * 2 + 1][1])
                    : "r"(addr));
            }
#define MMA(ar, br) \
    asm volatile("mma.sync.aligned.m16n8k16.row.col.f32.f16.f16.f32 " \
        "{%0,%1,%2,%3}, {%4,%5,%6,%7}, {%8,%9}, {%0,%1,%2,%3};" \
        : "+f"(acc[mf][nf][0]), "+f"(acc[mf][nf][1]), \
          "+f"(acc[mf][nf][2]), "+f"(acc[mf][nf][3]) \
        : "r"((ar)[0]), "r"((ar)[1]), "r"((ar)[2]), "r"((ar)[3]), \
          "r"((br)[0]), "r"((br)[1]))
#pragma unroll
            for (int mf = 0; mf < 2; mf++)
#pragma unroll
                for (int nf = 0; nf < 8; nf++) {
                    MMA(ah[mf], bh[nf]);
                    MMA(al[mf], bh[nf]);
                }
#undef MMA
        }

        // ---- epilogue at last k-chunk of each basis ----
        if (kc == 3) {
            const int b = bgrp * 3 + (j >> 2);
            if (b < 8) {
#pragma unroll
                for (int mf = 0; mf < 2; mf++) {
                    int r1 = m0 + wm * 32 + mf * 16 + (lane >> 2);
                    int r2 = r1 + 8;
#pragma unroll
                    for (int nf = 0; nf < 8; nf++) {
                        int col = wn * 64 + nf * 8 + (lane & 3) * 2;
                        if (r1 < N_NODES)
                            *(__half2*)(g_xbh + (size_t)r1 * (NB * D) + b * D + col) =
                                __floats2half2_rn(acc[mf][nf][0], acc[mf][nf][1]);
                        if (r2 < N_NODES)
                            *(__half2*)(g_xbh + (size_t)r2 * (NB * D) + b * D + col) =
                                __floats2half2_rn(acc[mf][nf][2], acc[mf][nf][3]);
                    }
                }
                float ad[4] = {0.f, 0.f, 0.f, 0.f};
#pragma unroll
                for (int mf = 0; mf < 2; mf++)
#pragma unroll
                    for (int nf = 0; nf < 8; nf++) {
                        int col = wn * 64 + nf * 8 + (lane & 3) * 2;
                        float a0 = atts[col], a1 = atts[col + 1];
                        ad[mf * 2 + 0] = fmaf(a0, acc[mf][nf][0], fmaf(a1, acc[mf][nf][1], ad[mf * 2 + 0]));
                        ad[mf * 2 + 1] = fmaf(a0, acc[mf][nf][2], fmaf(a1, acc[mf][nf][3], ad[mf * 2 + 1]));
                    }
#pragma unroll
                for (int off = 1; off <= 2; off <<= 1)
#pragma unroll
                    for (int q = 0; q < 4; q++) ad[q] += __shfl_xor_sync(0xffffffffu, ad[q], off);
                if ((lane & 3) == 0) {
                    int rbase = m0 + wm * 32 + (lane >> 2);
#pragma unroll
                    for (int mf = 0; mf < 2; mf++) {
                        int g1 = rbase + mf * 16;
                        if (g1 < N_NODES) atomicAdd(&g_attdot[(size_t)g1 * NB + b], ad[mf * 2 + 0]);
                        if (g1 + 8 < N_NODES) atomicAdd(&g_attdot[(size_t)(g1 + 8) * NB + b], ad[mf * 2 + 1]);
                    }
                }
            } else {
#pragma unroll
                for (int mf = 0; mf < 2; mf++) {
                    int r1 = m0 + wm * 32 + mf * 16 + (lane >> 2);
                    int r2 = r1 + 8;
#pragma unroll
                    for (int nf = 0; nf < 8; nf++) {
                        int col = wn * 64 + nf * 8 + (lane & 3) * 2;
                        if (r1 < N_NODES)
                            *(float2*)(g_xloop + (size_t)r1 * D + col) =
                                make_float2(acc[mf][nf][0], acc[mf][nf][1]);
                        if (r2 < N_NODES)
                            *(float2*)(g_xloop + (size_t)r2 * D + col) =
                                make_float2(acc[mf][nf][2], acc[mf][nf][3]);
                    }
                }
            }
        }
    }
}

// ---------------- CSR build ----------------
__global__ __launch_bounds__(256) void k_hist(const int* __restrict__ src) {
    int e = blockIdx.x * blockDim.x + threadIdx.x;
    if (e >= N_EDGES) return;
    atomicAdd(&g_cnt[src[e]], 1);
}

__global__ __launch_bounds__(1024) void k_scan() {
    __shared__ int ssum[1024];
    const int T = 1024, C = (N_NODES + T - 1) / T;   // 40
    int t = threadIdx.x;
    int lo = t * C, hi = min(lo + C, N_NODES);
    int s = 0;
    for (int i = lo; i < hi; i++) s += g_cnt[i];
    ssum[t] = s;
    __syncthreads();
    for (int off = 1; off < T; off <<= 1) {
        int u = (t >= off) ? ssum[t - off] : 0;
        __syncthreads();
        ssum[t] += u;
        __syncthreads();
    }
    int run = ssum[t] - s;   // exclusive prefix
    for (int i = lo; i < hi; i++) {
        g_off[i] = run;
        g_cur[i] = run;
        run += g_cnt[i];
    }
    if (t == 0) g_off[N_NODES] = N_EDGES;
}

__global__ __launch_bounds__(256) void k_scatter(const int* __restrict__ src,
                                                 const int* __restrict__ dst,
                                                 const int* __restrict__ rel) {
    int e = blockIdx.x * blockDim.x + threadIdx.x;
    if (e >= N_EDGES) return;
    int pos = atomicAdd(&g_cur[src[e]], 1);
    g_pk2[pos] = dst[e] * 32 + rel[e];
    g_eid2[pos] = e;
}

// ---------------- s[n,r] = sum_b coef[r,b] * attdot[n,b] ----------------
__global__ __launch_bounds__(256) void k_s2(const float* __restrict__ coef) {
    int t = blockIdx.x * blockDim.x + threadIdx.x;
    int node = t >> 5;
    int r = t & 31;
    if (node >= N_NODES) return;
    const float* ad = g_attdot + (size_t)node * NB;
    float s = 0.f;
#pragma unroll
    for (int b = 0; b < NB; b++) s = fmaf(coef[r * NB + b], ad[b], s);
    g_s[(size_t)node * R + r] = s;
}

// ---------------- edge pass 1 ----------------
__global__ __launch_bounds__(256) void k_edge1(const int* __restrict__ src,
                                               const int* __restrict__ dst,
                                               const int* __restrict__ rel) {
    int e = blockIdx.x * blockDim.x + threadIdx.x;
    if (e >= N_EDGES) return;
    int sN = src[e], dN = dst[e], rr = rel[e];
    float sc = g_s[(size_t)sN * R + rr] + g_s[(size_t)dN * R + rr];
    sc = (sc >= 0.f) ? sc : 0.01f * sc;
    float ez = expf(sc);
    g_ex[e] = ez;
    atomicAdd(&g_denom[dN], ez);
}

// ---------------- normalized weights in CSR order ----------------
__global__ __launch_bounds__(256) void k_wnorm() {
    int j = blockIdx.x * blockDim.x + threadIdx.x;
    if (j >= N_EDGES) return;
    int e = g_eid2[j];
    int dN = g_pk2[j] >> 5;
    g_w2[j] = g_ex[e] / g_denom[dN];
}

// ---------------- edge pass 2: CSR by src, warp per node ----------------
__global__ __launch_bounds__(256) void k_edge2(const float* __restrict__ coef) {
    int n = (blockIdx.x * blockDim.x + threadIdx.x) >> 5;
    int lane = threadIdx.x & 31;
    if (n >= N_NODES) return;
    int beg = g_off[n], end = g_off[n + 1];
    if (beg == end) return;
    const uint2* xp = (const uint2*)(g_xbh + (size_t)n * (NB * D)) + lane;
    float f[NB][4];
#pragma unroll
    for (int b = 0; b < NB; b++) {
        uint2 u = xp[b * 32];
        float2 f0 = __half22float2(*(const __half2*)&u.x);
        float2 f1 = __half22float2(*(const __half2*)&u.y);
        f[b][0] = f0.x; f[b][1] = f0.y; f[b][2] = f1.x; f[b][3] = f1.y;
    }
#pragma unroll 2
    for (int j = beg; j < end; j++) {
        int pk = g_pk2[j];
        float w = g_w2[j];
        int dN = pk >> 5, rr = pk & 31;
        const float4* cp = (const float4*)(coef + rr * NB);
        float4 c0 = cp[0], c1 = cp[1];
        float4 acc;
        acc.x = c0.x * f[0][0]; acc.y = c0.x * f[0][1]; acc.z = c0.x * f[0][2]; acc.w = c0.x * f[0][3];
        acc.x = fmaf(c0.y, f[1][0], acc.x); acc.y = fmaf(c0.y, f[1][1], acc.y);
        acc.z = fmaf(c0.y, f[1][2], acc.z); acc.w = fmaf(c0.y, f[1][3], acc.w);
        acc.x = fmaf(c0.z, f[2][0], acc.x); acc.y = fmaf(c0.z, f[2][1], acc.y);
        acc.z = fmaf(c0.z, f[2][2], acc.z); acc.w = fmaf(c0.z, f[2][3], acc.w);
        acc.x = fmaf(c0.w, f[3][0], acc.x); acc.y = fmaf(c0.w, f[3][1], acc.y);
        acc.z = fmaf(c0.w, f[3][2], acc.z); acc.w = fmaf(c0.w, f[3][3], acc.w);
        acc.x = fmaf(c1.x, f[4][0], acc.x); acc.y = fmaf(c1.x, f[4][1], acc.y);
        acc.z = fmaf(c1.x, f[4][2], acc.z); acc.w = fmaf(c1.x, f[4][3], acc.w);
        acc.x = fmaf(c1.y, f[5][0], acc.x); acc.y = fmaf(c1.y, f[5][1], acc.y);
        acc.z = fmaf(c1.y, f[5][2], acc.z); acc.w = fmaf(c1.y, f[5][3], acc.w);
        acc.x = fmaf(c1.z, f[6][0], acc.x); acc.y = fmaf(c1.z, f[6][1], acc.y);
        acc.z = fmaf(c1.z, f[6][2], acc.z); acc.w = fmaf(c1.z, f[6][3], acc.w);
        acc.x = fmaf(c1.w, f[7][0], acc.x); acc.y = fmaf(c1.w, f[7][1], acc.y);
        acc.z = fmaf(c1.w, f[7][2], acc.z); acc.w = fmaf(c1.w, f[7][3], acc.w);
        acc.x *= w; acc.y *= w; acc.z *= w; acc.w *= w;
        atomicAdd((float4*)(g_accum + (size_t)dN * D + lane * 4), acc);
    }
}

// ---------------- column stats (bias cancels in BN; ft not materialized) ----------------
__global__ __launch_bounds__(128) void k_ft(const float* __restrict__ norm) {
    int o = threadIdx.x;
    float lsum = 0.f, lsq = 0.f;
    for (int n = blockIdx.x; n < N_NODES; n += gridDim.x) {
        float v = g_accum[(size_t)n * D + o] * norm[n] + g_xloop[(size_t)n * D + o];
        lsum += v;
        lsq += v * v;
    }
    atomicAdd(&g_colsum[o], lsum);
    atomicAdd(&g_colsumsq[o], lsq);
}

// ---------------- BN finalize ----------------
__global__ void k_bn(const float* __restrict__ gamma, const float* __restrict__ beta) {
    int o = threadIdx.x;
    float mu = g_colsum[o] / (float)N_NODES;
    float var = g_colsumsq[o] / (float)N_NODES - mu * mu;
    float inv = rsqrtf(var + 1e-5f);
    float sc = gamma[o] * inv;
    g_scale[o] = sc;
    g_shift[o] = beta[o] - mu * sc;
}

// ---------------- output: recompute ft, scale-shift, relu ----------------
__global__ __launch_bounds__(256) void k_out(const float* __restrict__ norm,
                                             float* __restrict__ out) {
    int i = blockIdx.x * blockDim.x + threadIdx.x;
    int total = N_NODES * D / 4;
    if (i >= total) return;
    float nm = norm[(i * 4) >> 7];
    float4 a = ((const float4*)g_accum)[i];
    float4 xl = ((const float4*)g_xloop)[i];
    int o = (i * 4) & (D - 1);
    float4 r;
    r.x = fmaxf(0.f, (a.x * nm + xl.x) * g_scale[o + 0] + g_shift[o + 0]);
    r.y = fmaxf(0.f, (a.y * nm + xl.y) * g_scale[o + 1] + g_shift[o + 1]);
    r.z = fmaxf(0.f, (a.z * nm + xl.z) * g_scale[o + 2] + g_shift[o + 2]);
    r.w = fmaxf(0.f, (a.w * nm + xl.w) * g_scale[o + 3] + g_shift[o + 3]);
    ((float4*)out)[i] = r;
}

extern "C" void kernel_launch(void* const* d_in, const int* in_sizes, int n_in,
                              void* d_out, int out_size) {
    const float* x       = (const float*)d_in[0];
    const float* norm    = (const float*)d_in[1];
    const int*   esrc    = (const int*)d_in[2];
    const int*   edst    = (const int*)d_in[3];
    const int*   erel    = (const int*)d_in[4];
    const float* w_loop  = (const float*)d_in[5];
    const float* w_bases = (const float*)d_in[6];
    const float* coef    = (const float*)d_in[7];
    const float* att     = (const float*)d_in[8];
    // d_in[9] = w_bias: cancels inside BatchNorm, unused
    const float* gamma   = (const float*)d_in[10];
    const float* beta    = (const float*)d_in[11];
    float* out = (float*)d_out;

    cudaFuncSetAttribute(k_gemm_mma, cudaFuncAttributeMaxDynamicSharedMemorySize, SMEM_GEMM);

    k_prep<<<2048, 256>>>(x, w_bases, w_loop);

    k_hist<<<(N_EDGES + 255) / 256, 256>>>(esrc);
    k_scan<<<1, 1024>>>();
    k_scatter<<<(N_EDGES + 255) / 256, 256>>>(esrc, edst, erel);

    dim3 gg((N_NODES + 127) / 128, 3);
    k_gemm_mma<<<gg, 256, SMEM_GEMM>>>(att);

    k_s2<<<(N_NODES * 32 + 255) / 256, 256>>>(coef);
    k_edge1<<<(N_EDGES + 255) / 256, 256>>>(esrc, edst, erel);
    k_wnorm<<<(N_EDGES + 255) / 256, 256>>>();
    k_edge2<<<(N_NODES * 32 + 255) / 256, 256>>>(coef);
    k_ft<<<512, 128>>>(norm);
    k_bn<<<1, 128>>>(gamma, beta);
    k_out<<<(N_NODES * D / 4 + 255) / 256, 256>>>(norm, out);
}

// round 9
// speedup vs baseline: 1.2077x; 1.0172x over previous
#include <cuda_runtime.h>
#include <cuda_fp16.h>
#include <cstdint>
#include <math.h>

#define N_NODES 40000
#define N_EDGES 640000
#define D 128
#define R 32
#define NB 8

// ---- scratch (static device globals; no runtime allocation) ----
__device__ __half g_xbh[(size_t)N_NODES * NB * D];  // 82 MB: bases 0-7, fp16
__device__ float g_xloop[(size_t)N_NODES * D];      // 20.5 MB: loop block fp32
__device__ float g_s[(size_t)N_NODES * R];          // 5.1 MB
__device__ float g_attdot[(size_t)N_NODES * NB];    // 1.28 MB
__device__ float g_ex[N_EDGES];
__device__ float g_denom[N_NODES];
__device__ float g_accum[(size_t)N_NODES * D];      // 20.5 MB
__device__ float g_colsum[D];
__device__ float g_colsumsq[D];
__device__ float g_scale[D];
__device__ float g_shift[D];
__device__ __half g_xh[(size_t)N_NODES * D];        // x (fp16)
__device__ __half g_wth[9 * D * D];                 // [b][n][k]  (W^T, fp16)
// CSR by src
__device__ int g_cnt[N_NODES];
__device__ int g_cur[N_NODES];
__device__ int g_off[N_NODES + 1];
__device__ int g_pk2[N_EDGES];    // dst*32 + rel, CSR order
__device__ int g_eid2[N_EDGES];   // original edge id, CSR order

// ================= fused prep: zero + convert x + convert W =================
__global__ __launch_bounds__(256) void k_prep(const float* __restrict__ x,
                                              const float* __restrict__ w_bases,
                                              const float* __restrict__ w_loop) {
    int idx0 = blockIdx.x * blockDim.x + threadIdx.x;
    int stride = gridDim.x * blockDim.x;
    for (int i = idx0; i < N_NODES * D; i += stride) {
        g_accum[i] = 0.f;
        g_xh[i] = __float2half_rn(x[i]);
    }
    for (int i = idx0; i < 9 * D * D; i += stride) {
        int b = i >> 14;
        int rem = i & 16383;
        int n = rem >> 7;
        int k = rem & 127;
        float v = (b < 8) ? w_bases[(b << 14) + k * D + n] : w_loop[k * D + n];
        g_wth[i] = __float2half_rn(v);
    }
    for (int i = idx0; i < N_NODES * NB; i += stride) g_attdot[i] = 0.f;
    for (int i = idx0; i < N_NODES; i += stride) { g_denom[i] = 0.f; g_cnt[i] = 0; }
    if (idx0 < D) { g_colsum[idx0] = 0.f; g_colsumsq[idx0] = 0.f; }
}

// ================= mma.sync fp16 GEMM, A-resident, 3 bases per CTA =================
// Grid: (313 m-tiles, 3 base-groups). CTA = 256 thr = 8 warps (4 m x 2 n).
// A (all 4 k-chunks) resident in smem; B tile double-buffered per (basis, kc).

#define PAD 40
#define TILE_H (128 * PAD)          // halfs per tile
#define TILE_B (TILE_H * 2)         // bytes per tile (10240)
#define SMEM_GEMM (512 + 6 * TILE_B)   // 4 A tiles + 2 B buffers + atts

__device__ __forceinline__ void cpa16(uint32_t dst, const void* src, int sz) {
    asm volatile("cp.async.ca.shared.global [%0], [%1], 16, %2;"
                 :: "r"(dst), "l"(src), "r"(sz));
}

__global__ __launch_bounds__(256, 2) void k_gemm_mma(const float* __restrict__ att) {
    extern __shared__ __align__(16) char dsm[];
    float* atts = (float*)dsm;
    __half* tiles = (__half*)(dsm + 512);

    const int tid = threadIdx.x;
    const int lane = tid & 31;
    const int wid = tid >> 5;
    const int wm = wid & 3;       // 0..3 : 32-row strip
    const int wn = wid >> 2;      // 0..1 : 64-col strip
    const int m0 = blockIdx.x * 128;
    const int bgrp = blockIdx.y;  // 0..2 -> bases bgrp*3 .. bgrp*3+2

    if (tid < 128) atts[tid] = att[tid];

    const int fi_row[2] = { (0 * 256 + tid) >> 2, (1 * 256 + tid) >> 2 };
    const int fi_c8[2]  = { ((0 * 256 + tid) & 3) * 8, ((1 * 256 + tid) & 3) * 8 };

    // ---- load all A tiles (4 kc) ----
#pragma unroll
    for (int kc = 0; kc < 4; kc++) {
        __half* Ahi = tiles + kc * TILE_H;
#pragma unroll
        for (int l = 0; l < 2; l++) {
            int row = fi_row[l], c8 = fi_c8[l];
            int g = m0 + row;
            bool ok = g < N_NODES;
            int gc = ok ? g : 0;
            int sz = ok ? 16 : 0;
            cpa16((uint32_t)__cvta_generic_to_shared(Ahi + row * PAD + c8),
                  g_xh + (size_t)gc * D + kc * 32 + c8, sz);
        }
    }
    asm volatile("cp.async.commit_group;" ::: "memory");

#define ISSUE_B(jj, s) do {                                                       \
    const int _b = bgrp * 3 + ((jj) >> 2);                                        \
    const int _k0 = ((jj) & 3) * 32;                                              \
    const __half* _Bg = g_wth + _b * (D * D);                                     \
    __half* _Bs = tiles + (4 + (s)) * TILE_H;                                     \
    _Pragma("unroll")                                                             \
    for (int _l = 0; _l < 2; _l++) {                                              \
        int _row = fi_row[_l], _c8 = fi_c8[_l];                                   \
        cpa16((uint32_t)__cvta_generic_to_shared(_Bs + _row * PAD + _c8),         \
              _Bg + _row * D + _k0 + _c8, 16);                                    \
    }                                                                             \
    asm volatile("cp.async.commit_group;" ::: "memory");                          \
} while (0)

    ISSUE_B(0, 0);

    const int a_row = wm * 32 + (lane & 15);
    const int a_cb = (lane >> 4) << 3;
    const int b_row = wn * 64 + (lane & 7) + ((lane >> 4) << 3);
    const int b_cb = (lane & 8);

    float acc[2][8][4];

#pragma unroll 1
    for (int j = 0; j < 12; j++) {
        const int kc = j & 3;
        const int s = j & 1;
        __syncthreads();               // prior consumption of buffer s^1 finished
        if (j < 11) {
            ISSUE_B(j + 1, s ^ 1);
            asm volatile("cp.async.wait_group 1;" ::: "memory");
        } else {
            asm volatile("cp.async.wait_group 0;" ::: "memory");
        }
        __syncthreads();               // fills visible to all warps

        if (kc == 0) {
#pragma unroll
            for (int mf = 0; mf < 2; mf++)
#pragma unroll
                for (int nf = 0; nf < 8; nf++)
#pragma unroll
                    for (int r = 0; r < 4; r++) acc[mf][nf][r] = 0.f;
        }

        const __half* Ah = tiles + kc * TILE_H;
        const __half* Bh = tiles + (4 + s) * TILE_H;

#pragma unroll
        for (int ks = 0; ks < 2; ks++) {
            const int kk = ks * 16;
            uint32_t ah[2][4], bh[8][2];
#pragma unroll
            for (int mf = 0; mf < 2; mf++) {
                uint32_t addr = (uint32_t)__cvta_generic_to_shared(
                    Ah + (a_row + mf * 16) * PAD + kk + a_cb);
                asm volatile("ldmatrix.sync.aligned.m8n8.x4.shared.b16 {%0,%1,%2,%3}, [%4];"
                    : "=r"(ah[mf][0]), "=r"(ah[mf][1]), "=r"(ah[mf][2]), "=r"(ah[mf][3])
                    : "r"(addr));
            }
#pragma unroll
            for (int nf2 = 0; nf2 < 4; nf2++) {
                uint32_t addr = (uint32_t)__cvta_generic_to_shared(
                    Bh + (b_row + nf2 * 16) * PAD + kk + b_cb);
                asm volatile("ldmatrix.sync.aligned.m8n8.x4.shared.b16 {%0,%1,%2,%3}, [%4];"
                    : "=r"(bh[nf2 * 2][0]), "=r"(bh[nf2 * 2][1]),
                      "=r"(bh[nf2 * 2 + 1][0]), "=r"(bh[nf2 * 2 + 1][1])
                    : "r"(addr));
            }
#define MMA(ar, br) \
    asm volatile("mma.sync.aligned.m16n8k16.row.col.f32.f16.f16.f32 " \
        "{%0,%1,%2,%3}, {%4,%5,%6,%7}, {%8,%9}, {%0,%1,%2,%3};" \
        : "+f"(acc[mf][nf][0]), "+f"(acc[mf][nf][1]), \
          "+f"(acc[mf][nf][2]), "+f"(acc[mf][nf][3]) \
        : "r"((ar)[0]), "r"((ar)[1]), "r"((ar)[2]), "r"((ar)[3]), \
          "r"((br)[0]), "r"((br)[1]))
#pragma unroll
            for (int mf = 0; mf < 2; mf++)
#pragma unroll
                for (int nf = 0; nf < 8; nf++) MMA(ah[mf], bh[nf]);
#undef MMA
        }

        // ---- epilogue at last k-chunk of each basis ----
        if (kc == 3) {
            const int b = bgrp * 3 + (j >> 2);
            if (b < 8) {
#pragma unroll
                for (int mf = 0; mf < 2; mf++) {
                    int r1 = m0 + wm * 32 + mf * 16 + (lane >> 2);
                    int r2 = r1 + 8;
#pragma unroll
                    for (int nf = 0; nf < 8; nf++) {
                        int col = wn * 64 + nf * 8 + (lane & 3) * 2;
                        if (r1 < N_NODES)
                            *(__half2*)(g_xbh + (size_t)r1 * (NB * D) + b * D + col) =
                                __floats2half2_rn(acc[mf][nf][0], acc[mf][nf][1]);
                        if (r2 < N_NODES)
                            *(__half2*)(g_xbh + (size_t)r2 * (NB * D) + b * D + col) =
                                __floats2half2_rn(acc[mf][nf][2], acc[mf][nf][3]);
                    }
                }
                float ad[4] = {0.f, 0.f, 0.f, 0.f};
#pragma unroll
                for (int mf = 0; mf < 2; mf++)
#pragma unroll
                    for (int nf = 0; nf < 8; nf++) {
                        int col = wn * 64 + nf * 8 + (lane & 3) * 2;
                        float a0 = atts[col], a1 = atts[col + 1];
                        ad[mf * 2 + 0] = fmaf(a0, acc[mf][nf][0], fmaf(a1, acc[mf][nf][1], ad[mf * 2 + 0]));
                        ad[mf * 2 + 1] = fmaf(a0, acc[mf][nf][2], fmaf(a1, acc[mf][nf][3], ad[mf * 2 + 1]));
                    }
#pragma unroll
                for (int off = 1; off <= 2; off <<= 1)
#pragma unroll
                    for (int q = 0; q < 4; q++) ad[q] += __shfl_xor_sync(0xffffffffu, ad[q], off);
                if ((lane & 3) == 0) {
                    int rbase = m0 + wm * 32 + (lane >> 2);
#pragma unroll
                    for (int mf = 0; mf < 2; mf++) {
                        int g1 = rbase + mf * 16;
                        if (g1 < N_NODES) atomicAdd(&g_attdot[(size_t)g1 * NB + b], ad[mf * 2 + 0]);
                        if (g1 + 8 < N_NODES) atomicAdd(&g_attdot[(size_t)(g1 + 8) * NB + b], ad[mf * 2 + 1]);
                    }
                }
            } else {
#pragma unroll
                for (int mf = 0; mf < 2; mf++) {
                    int r1 = m0 + wm * 32 + mf * 16 + (lane >> 2);
                    int r2 = r1 + 8;
#pragma unroll
                    for (int nf = 0; nf < 8; nf++) {
                        int col = wn * 64 + nf * 8 + (lane & 3) * 2;
                        if (r1 < N_NODES)
                            *(float2*)(g_xloop + (size_t)r1 * D + col) =
                                make_float2(acc[mf][nf][0], acc[mf][nf][1]);
                        if (r2 < N_NODES)
                            *(float2*)(g_xloop + (size_t)r2 * D + col) =
                                make_float2(acc[mf][nf][2], acc[mf][nf][3]);
                    }
                }
            }
        }
    }
}

// ---------------- CSR build ----------------
__global__ __launch_bounds__(256) void k_hist(const int* __restrict__ src) {
    int e = blockIdx.x * blockDim.x + threadIdx.x;
    if (e >= N_EDGES) return;
    atomicAdd(&g_cnt[src[e]], 1);
}

__global__ __launch_bounds__(1024) void k_scan() {
    __shared__ int ssum[1024];
    const int T = 1024, C = (N_NODES + T - 1) / T;   // 40
    int t = threadIdx.x;
    int lo = t * C, hi = min(lo + C, N_NODES);
    int s = 0;
    for (int i = lo; i < hi; i++) s += g_cnt[i];
    ssum[t] = s;
    __syncthreads();
    for (int off = 1; off < T; off <<= 1) {
        int u = (t >= off) ? ssum[t - off] : 0;
        __syncthreads();
        ssum[t] += u;
        __syncthreads();
    }
    int run = ssum[t] - s;   // exclusive prefix
    for (int i = lo; i < hi; i++) {
        g_off[i] = run;
        g_cur[i] = run;
        run += g_cnt[i];
    }
    if (t == 0) g_off[N_NODES] = N_EDGES;
}

__global__ __launch_bounds__(256) void k_scatter(const int* __restrict__ src,
                                                 const int* __restrict__ dst,
                                                 const int* __restrict__ rel) {
    int e = blockIdx.x * blockDim.x + threadIdx.x;
    if (e >= N_EDGES) return;
    int pos = atomicAdd(&g_cur[src[e]], 1);
    g_pk2[pos] = dst[e] * 32 + rel[e];
    g_eid2[pos] = e;
}

// ---------------- s[n,r] = sum_b coef[r,b] * attdot[n,b] ----------------
__global__ __launch_bounds__(256) void k_s2(const float* __restrict__ coef) {
    int t = blockIdx.x * blockDim.x + threadIdx.x;
    int node = t >> 5;
    int r = t & 31;
    if (node >= N_NODES) return;
    const float* ad = g_attdot + (size_t)node * NB;
    float s = 0.f;
#pragma unroll
    for (int b = 0; b < NB; b++) s = fmaf(coef[r * NB + b], ad[b], s);
    g_s[(size_t)node * R + r] = s;
}

// ---------------- edge pass 1 ----------------
__global__ __launch_bounds__(256) void k_edge1(const int* __restrict__ src,
                                               const int* __restrict__ dst,
                                               const int* __restrict__ rel) {
    int e = blockIdx.x * blockDim.x + threadIdx.x;
    if (e >= N_EDGES) return;
    int sN = src[e], dN = dst[e], rr = rel[e];
    float sc = g_s[(size_t)sN * R + rr] + g_s[(size_t)dN * R + rr];
    sc = (sc >= 0.f) ? sc : 0.01f * sc;
    float ez = expf(sc);
    g_ex[e] = ez;
    atomicAdd(&g_denom[dN], ez);
}

// ---------------- edge pass 2: CSR by src, warp per node, fused wnorm ----------------
__global__ __launch_bounds__(256) void k_edge2(const float* __restrict__ coef) {
    int n = (blockIdx.x * blockDim.x + threadIdx.x) >> 5;
    int lane = threadIdx.x & 31;
    if (n >= N_NODES) return;
    int beg = g_off[n], end = g_off[n + 1];
    if (beg == end) return;
    const uint2* xp = (const uint2*)(g_xbh + (size_t)n * (NB * D)) + lane;
    float f[NB][4];
#pragma unroll
    for (int b = 0; b < NB; b++) {
        uint2 u = xp[b * 32];
        float2 f0 = __half22float2(*(const __half2*)&u.x);
        float2 f1 = __half22float2(*(const __half2*)&u.y);
        f[b][0] = f0.x; f[b][1] = f0.y; f[b][2] = f1.x; f[b][3] = f1.y;
    }
#pragma unroll 2
    for (int j = beg; j < end; j++) {
        int pk = g_pk2[j];
        int e = g_eid2[j];
        int dN = pk >> 5, rr = pk & 31;
        float w = g_ex[e] / g_denom[dN];
        const float4* cp = (const float4*)(coef + rr * NB);
        float4 c0 = cp[0], c1 = cp[1];
        float4 acc;
        acc.x = c0.x * f[0][0]; acc.y = c0.x * f[0][1]; acc.z = c0.x * f[0][2]; acc.w = c0.x * f[0][3];
        acc.x = fmaf(c0.y, f[1][0], acc.x); acc.y = fmaf(c0.y, f[1][1], acc.y);
        acc.z = fmaf(c0.y, f[1][2], acc.z); acc.w = fmaf(c0.y, f[1][3], acc.w);
        acc.x = fmaf(c0.z, f[2][0], acc.x); acc.y = fmaf(c0.z, f[2][1], acc.y);
        acc.z = fmaf(c0.z, f[2][2], acc.z); acc.w = fmaf(c0.z, f[2][3], acc.w);
        acc.x = fmaf(c0.w, f[3][0], acc.x); acc.y = fmaf(c0.w, f[3][1], acc.y);
        acc.z = fmaf(c0.w, f[3][2], acc.z); acc.w = fmaf(c0.w, f[3][3], acc.w);
        acc.x = fmaf(c1.x, f[4][0], acc.x); acc.y = fmaf(c1.x, f[4][1], acc.y);
        acc.z = fmaf(c1.x, f[4][2], acc.z); acc.w = fmaf(c1.x, f[4][3], acc.w);
        acc.x = fmaf(c1.y, f[5][0], acc.x); acc.y = fmaf(c1.y, f[5][1], acc.y);
        acc.z = fmaf(c1.y, f[5][2], acc.z); acc.w = fmaf(c1.y, f[5][3], acc.w);
        acc.x = fmaf(c1.z, f[6][0], acc.x); acc.y = fmaf(c1.z, f[6][1], acc.y);
        acc.z = fmaf(c1.z, f[6][2], acc.z); acc.w = fmaf(c1.z, f[6][3], acc.w);
        acc.x = fmaf(c1.w, f[7][0], acc.x); acc.y = fmaf(c1.w, f[7][1], acc.y);
        acc.z = fmaf(c1.w, f[7][2], acc.z); acc.w = fmaf(c1.w, f[7][3], acc.w);
        acc.x *= w; acc.y *= w; acc.z *= w; acc.w *= w;
        atomicAdd((float4*)(g_accum + (size_t)dN * D + lane * 4), acc);
    }
}

// ---------------- column stats (bias cancels in BN; ft not materialized) ----------------
__global__ __launch_bounds__(128) void k_ft(const float* __restrict__ norm) {
    int o = threadIdx.x;
    float lsum = 0.f, lsq = 0.f;
    for (int n = blockIdx.x; n < N_NODES; n += gridDim.x) {
        float v = g_accum[(size_t)n * D + o] * norm[n] + g_xloop[(size_t)n * D + o];
        lsum += v;
        lsq += v * v;
    }
    atomicAdd(&g_colsum[o], lsum);
    atomicAdd(&g_colsumsq[o], lsq);
}

// ---------------- BN finalize ----------------
__global__ void k_bn(const float* __restrict__ gamma, const float* __restrict__ beta) {
    int o = threadIdx.x;
    float mu = g_colsum[o] / (float)N_NODES;
    float var = g_colsumsq[o] / (float)N_NODES - mu * mu;
    float inv = rsqrtf(var + 1e-5f);
    float sc = gamma[o] * inv;
    g_scale[o] = sc;
    g_shift[o] = beta[o] - mu * sc;
}

// ---------------- output: recompute ft, scale-shift, relu ----------------
__global__ __launch_bounds__(256) void k_out(const float* __restrict__ norm,
                                             float* __restrict__ out) {
    int i = blockIdx.x * blockDim.x + threadIdx.x;
    int total = N_NODES * D / 4;
    if (i >= total) return;
    float nm = norm[(i * 4) >> 7];
    float4 a = ((const float4*)g_accum)[i];
    float4 xl = ((const float4*)g_xloop)[i];
    int o = (i * 4) & (D - 1);
    float4 r;
    r.x = fmaxf(0.f, (a.x * nm + xl.x) * g_scale[o + 0] + g_shift[o + 0]);
    r.y = fmaxf(0.f, (a.y * nm + xl.y) * g_scale[o + 1] + g_shift[o + 1]);
    r.z = fmaxf(0.f, (a.z * nm + xl.z) * g_scale[o + 2] + g_shift[o + 2]);
    r.w = fmaxf(0.f, (a.w * nm + xl.w) * g_scale[o + 3] + g_shift[o + 3]);
    ((float4*)out)[i] = r;
}

extern "C" void kernel_launch(void* const* d_in, const int* in_sizes, int n_in,
                              void* d_out, int out_size) {
    const float* x       = (const float*)d_in[0];
    const float* norm    = (const float*)d_in[1];
    const int*   esrc    = (const int*)d_in[2];
    const int*   edst    = (const int*)d_in[3];
    const int*   erel    = (const int*)d_in[4];
    const float* w_loop  = (const float*)d_in[5];
    const float* w_bases = (const float*)d_in[6];
    const float* coef    = (const float*)d_in[7];
    const float* att     = (const float*)d_in[8];
    // d_in[9] = w_bias: cancels inside BatchNorm, unused
    const float* gamma   = (const float*)d_in[10];
    const float* beta    = (const float*)d_in[11];
    float* out = (float*)d_out;

    cudaFuncSetAttribute(k_gemm_mma, cudaFuncAttributeMaxDynamicSharedMemorySize, SMEM_GEMM);

    k_prep<<<2048, 256>>>(x, w_bases, w_loop);

    k_hist<<<(N_EDGES + 255) / 256, 256>>>(esrc);
    k_scan<<<1, 1024>>>();
    k_scatter<<<(N_EDGES + 255) / 256, 256>>>(esrc, edst, erel);

    dim3 gg((N_NODES + 127) / 128, 3);
    k_gemm_mma<<<gg, 256, SMEM_GEMM>>>(att);

    k_s2<<<(N_NODES * 32 + 255) / 256, 256>>>(coef);
    k_edge1<<<(N_EDGES + 255) / 256, 256>>>(esrc, edst, erel);
    k_edge2<<<(N_NODES * 32 + 255) / 256, 256>>>(coef);
    k_ft<<<512, 128>>>(norm);
    k_bn<<<1, 128>>>(gamma, beta);
    k_out<<<(N_NODES * D / 4 + 255) / 256, 256>>>(norm, out);
}

// round 11
// speedup vs baseline: 1.2532x; 1.0377x over previous
#include <cuda_runtime.h>
#include <cuda_fp16.h>
#include <cstdint>
#include <math.h>

#define N_NODES 40000
#define N_EDGES 640000
#define D 128
#define R 32
#define NB 8

// ---- scratch (static device globals; no runtime allocation) ----
__device__ __half g_xbh[(size_t)N_NODES * NB * D];  // 82 MB: bases 0-7, fp16
__device__ float g_xloop[(size_t)N_NODES * D];      // 20.5 MB: loop block fp32
__device__ float g_s[(size_t)N_NODES * R];          // 5.1 MB
__device__ float g_attdot[(size_t)N_NODES * NB];    // 1.28 MB
__device__ float g_denom[N_NODES];
__device__ float g_accum[(size_t)N_NODES * D];      // 20.5 MB
__device__ float g_colsum[D];
__device__ float g_colsumsq[D];
__device__ float g_scale[D];
__device__ float g_shift[D];
__device__ __half g_xh[(size_t)N_NODES * D];        // x (fp16)
__device__ __half g_wth[9 * D * D];                 // [b][n][k]  (W^T, fp16)
// CSR by src
__device__ int g_cnt[N_NODES];
__device__ int g_cur[N_NODES];
__device__ int g_off[N_NODES + 1];
__device__ int g_pk2[N_EDGES];    // dst*32 + rel, CSR order
__device__ float g_w2[N_EDGES];   // exp(score), CSR order

// ================= fused prep: zero + convert x + convert W =================
__global__ __launch_bounds__(256) void k_prep(const float* __restrict__ x,
                                              const float* __restrict__ w_bases,
                                              const float* __restrict__ w_loop) {
    int idx0 = blockIdx.x * blockDim.x + threadIdx.x;
    int stride = gridDim.x * blockDim.x;
    for (int i = idx0; i < N_NODES * D; i += stride) {
        g_accum[i] = 0.f;
        g_xh[i] = __float2half_rn(x[i]);
    }
    for (int i = idx0; i < 9 * D * D; i += stride) {
        int b = i >> 14;
        int rem = i & 16383;
        int n = rem >> 7;
        int k = rem & 127;
        float v = (b < 8) ? w_bases[(b << 14) + k * D + n] : w_loop[k * D + n];
        g_wth[i] = __float2half_rn(v);
    }
    for (int i = idx0; i < N_NODES * NB; i += stride) g_attdot[i] = 0.f;
    for (int i = idx0; i < N_NODES; i += stride) { g_denom[i] = 0.f; g_cnt[i] = 0; }
    if (idx0 < D) { g_colsum[idx0] = 0.f; g_colsumsq[idx0] = 0.f; }
}

// ================= mma.sync fp16 GEMM, A-resident, 3 bases per CTA =================
// Grid: (313 m-tiles, 3 base-groups). CTA = 256 thr = 8 warps (4 m x 2 n).

#define PAD 40
#define TILE_H (128 * PAD)          // halfs per tile
#define TILE_B (TILE_H * 2)         // bytes per tile (10240)
#define SMEM_GEMM (512 + 6 * TILE_B)   // 4 A tiles + 2 B buffers + atts

__device__ __forceinline__ void cpa16(uint32_t dst, const void* src, int sz) {
    asm volatile("cp.async.ca.shared.global [%0], [%1], 16, %2;"
                 :: "r"(dst), "l"(src), "r"(sz));
}

__global__ __launch_bounds__(256, 2) void k_gemm_mma(const float* __restrict__ att) {
    extern __shared__ __align__(16) char dsm[];
    float* atts = (float*)dsm;
    __half* tiles = (__half*)(dsm + 512);

    const int tid = threadIdx.x;
    const int lane = tid & 31;
    const int wid = tid >> 5;
    const int wm = wid & 3;       // 0..3 : 32-row strip
    const int wn = wid >> 2;      // 0..1 : 64-col strip
    const int m0 = blockIdx.x * 128;
    const int bgrp = blockIdx.y;  // 0..2 -> bases bgrp*3 .. bgrp*3+2

    if (tid < 128) atts[tid] = att[tid];

    const int fi_row[2] = { (0 * 256 + tid) >> 2, (1 * 256 + tid) >> 2 };
    const int fi_c8[2]  = { ((0 * 256 + tid) & 3) * 8, ((1 * 256 + tid) & 3) * 8 };

    // ---- load all A tiles (4 kc) ----
#pragma unroll
    for (int kc = 0; kc < 4; kc++) {
        __half* Ahi = tiles + kc * TILE_H;
#pragma unroll
        for (int l = 0; l < 2; l++) {
            int row = fi_row[l], c8 = fi_c8[l];
            int g = m0 + row;
            bool ok = g < N_NODES;
            int gc = ok ? g : 0;
            int sz = ok ? 16 : 0;
            cpa16((uint32_t)__cvta_generic_to_shared(Ahi + row * PAD + c8),
                  g_xh + (size_t)gc * D + kc * 32 + c8, sz);
        }
    }
    asm volatile("cp.async.commit_group;" ::: "memory");

#define ISSUE_B(jj, s) do {                                                       \
    const int _b = bgrp * 3 + ((jj) >> 2);                                        \
    const int _k0 = ((jj) & 3) * 32;                                              \
    const __half* _Bg = g_wth + _b * (D * D);                                     \
    __half* _Bs = tiles + (4 + (s)) * TILE_H;                                     \
    _Pragma("unroll")                                                             \
    for (int _l = 0; _l < 2; _l++) {                                              \
        int _row = fi_row[_l], _c8 = fi_c8[_l];                                   \
        cpa16((uint32_t)__cvta_generic_to_shared(_Bs + _row * PAD + _c8),         \
              _Bg + _row * D + _k0 + _c8, 16);                                    \
    }                                                                             \
    asm volatile("cp.async.commit_group;" ::: "memory");                          \
} while (0)

    ISSUE_B(0, 0);

    const int a_row = wm * 32 + (lane & 15);
    const int a_cb = (lane >> 4) << 3;
    const int b_row = wn * 64 + (lane & 7) + ((lane >> 4) << 3);
    const int b_cb = (lane & 8);

    float acc[2][8][4];

#pragma unroll 1
    for (int j = 0; j < 12; j++) {
        const int kc = j & 3;
        const int s = j & 1;
        __syncthreads();
        if (j < 11) {
            ISSUE_B(j + 1, s ^ 1);
            asm volatile("cp.async.wait_group 1;" ::: "memory");
        } else {
            asm volatile("cp.async.wait_group 0;" ::: "memory");
        }
        __syncthreads();

        if (kc == 0) {
#pragma unroll
            for (int mf = 0; mf < 2; mf++)
#pragma unroll
                for (int nf = 0; nf < 8; nf++)
#pragma unroll
                    for (int r = 0; r < 4; r++) acc[mf][nf][r] = 0.f;
        }

        const __half* Ah = tiles + kc * TILE_H;
        const __half* Bh = tiles + (4 + s) * TILE_H;

#pragma unroll
        for (int ks = 0; ks < 2; ks++) {
            const int kk = ks * 16;
            uint32_t ah[2][4], bh[8][2];
#pragma unroll
            for (int mf = 0; mf < 2; mf++) {
                uint32_t addr = (uint32_t)__cvta_generic_to_shared(
                    Ah + (a_row + mf * 16) * PAD + kk + a_cb);
                asm volatile("ldmatrix.sync.aligned.m8n8.x4.shared.b16 {%0,%1,%2,%3}, [%4];"
                    : "=r"(ah[mf][0]), "=r"(ah[mf][1]), "=r"(ah[mf][2]), "=r"(ah[mf][3])
                    : "r"(addr));
            }
#pragma unroll
            for (int nf2 = 0; nf2 < 4; nf2++) {
                uint32_t addr = (uint32_t)__cvta_generic_to_shared(
                    Bh + (b_row + nf2 * 16) * PAD + kk + b_cb);
                asm volatile("ldmatrix.sync.aligned.m8n8.x4.shared.b16 {%0,%1,%2,%3}, [%4];"
                    : "=r"(bh[nf2 * 2][0]), "=r"(bh[nf2 * 2][1]),
                      "=r"(bh[nf2 * 2 + 1][0]), "=r"(bh[nf2 * 2 + 1][1])
                    : "r"(addr));
            }
#define MMA(ar, br) \
    asm volatile("mma.sync.aligned.m16n8k16.row.col.f32.f16.f16.f32 " \
        "{%0,%1,%2,%3}, {%4,%5,%6,%7}, {%8,%9}, {%0,%1,%2,%3};" \
        : "+f"(acc[mf][nf][0]), "+f"(acc[mf][nf][1]), \
          "+f"(acc[mf][nf][2]), "+f"(acc[mf][nf][3]) \
        : "r"((ar)[0]), "r"((ar)[1]), "r"((ar)[2]), "r"((ar)[3]), \
          "r"((br)[0]), "r"((br)[1]))
#pragma unroll
            for (int mf = 0; mf < 2; mf++)
#pragma unroll
                for (int nf = 0; nf < 8; nf++) MMA(ah[mf], bh[nf]);
#undef MMA
        }

        // ---- epilogue at last k-chunk of each basis ----
        if (kc == 3) {
            const int b = bgrp * 3 + (j >> 2);
            if (b < 8) {
#pragma unroll
                for (int mf = 0; mf < 2; mf++) {
                    int r1 = m0 + wm * 32 + mf * 16 + (lane >> 2);
                    int r2 = r1 + 8;
#pragma unroll
                    for (int nf = 0; nf < 8; nf++) {
                        int col = wn * 64 + nf * 8 + (lane & 3) * 2;
                        if (r1 < N_NODES)
                            *(__half2*)(g_xbh + (size_t)r1 * (NB * D) + b * D + col) =
                                __floats2half2_rn(acc[mf][nf][0], acc[mf][nf][1]);
                        if (r2 < N_NODES)
                            *(__half2*)(g_xbh + (size_t)r2 * (NB * D) + b * D + col) =
                                __floats2half2_rn(acc[mf][nf][2], acc[mf][nf][3]);
                    }
                }
                float ad[4] = {0.f, 0.f, 0.f, 0.f};
#pragma unroll
                for (int mf = 0; mf < 2; mf++)
#pragma unroll
                    for (int nf = 0; nf < 8; nf++) {
                        int col = wn * 64 + nf * 8 + (lane & 3) * 2;
                        float a0 = atts[col], a1 = atts[col + 1];
                        ad[mf * 2 + 0] = fmaf(a0, acc[mf][nf][0], fmaf(a1, acc[mf][nf][1], ad[mf * 2 + 0]));
                        ad[mf * 2 + 1] = fmaf(a0, acc[mf][nf][2], fmaf(a1, acc[mf][nf][3], ad[mf * 2 + 1]));
                    }
#pragma unroll
                for (int off = 1; off <= 2; off <<= 1)
#pragma unroll
                    for (int q = 0; q < 4; q++) ad[q] += __shfl_xor_sync(0xffffffffu, ad[q], off);
                if ((lane & 3) == 0) {
                    int rbase = m0 + wm * 32 + (lane >> 2);
#pragma unroll
                    for (int mf = 0; mf < 2; mf++) {
                        int g1 = rbase + mf * 16;
                        // two n-strip warps contribute halves: must accumulate
                        if (g1 < N_NODES) atomicAdd(&g_attdot[(size_t)g1 * NB + b], ad[mf * 2 + 0]);
                        if (g1 + 8 < N_NODES) atomicAdd(&g_attdot[(size_t)(g1 + 8) * NB + b], ad[mf * 2 + 1]);
                    }
                }
            } else {
#pragma unroll
                for (int mf = 0; mf < 2; mf++) {
                    int r1 = m0 + wm * 32 + mf * 16 + (lane >> 2);
                    int r2 = r1 + 8;
#pragma unroll
                    for (int nf = 0; nf < 8; nf++) {
                        int col = wn * 64 + nf * 8 + (lane & 3) * 2;
                        if (r1 < N_NODES)
                            *(float2*)(g_xloop + (size_t)r1 * D + col) =
                                make_float2(acc[mf][nf][0], acc[mf][nf][1]);
                        if (r2 < N_NODES)
                            *(float2*)(g_xloop + (size_t)r2 * D + col) =
                                make_float2(acc[mf][nf][2], acc[mf][nf][3]);
                    }
                }
            }
        }
    }
}

// ---------------- CSR build ----------------
__global__ __launch_bounds__(256) void k_hist(const int* __restrict__ src) {
    int e = blockIdx.x * blockDim.x + threadIdx.x;
    if (e >= N_EDGES) return;
    atomicAdd(&g_cnt[src[e]], 1);
}

__global__ __launch_bounds__(1024) void k_scan() {
    __shared__ int ssum[1024];
    const int T = 1024, C = (N_NODES + T - 1) / T;   // 40
    int t = threadIdx.x;
    int lo = t * C, hi = min(lo + C, N_NODES);
    int s = 0;
    for (int i = lo; i < hi; i++) s += g_cnt[i];
    ssum[t] = s;
    __syncthreads();
    for (int off = 1; off < T; off <<= 1) {
        int u = (t >= off) ? ssum[t - off] : 0;
        __syncthreads();
        ssum[t] += u;
        __syncthreads();
    }
    int run = ssum[t] - s;   // exclusive prefix
    for (int i = lo; i < hi; i++) {
        g_off[i] = run;
        g_cur[i] = run;
        run += g_cnt[i];
    }
    if (t == 0) g_off[N_NODES] = N_EDGES;
}

// ---------------- s[n,r] = sum_b coef[r,b] * attdot[n,b] ----------------
__global__ __launch_bounds__(256) void k_s2(const float* __restrict__ coef) {
    int t = blockIdx.x * blockDim.x + threadIdx.x;
    int node = t >> 5;
    int r = t & 31;
    if (node >= N_NODES) return;
    const float* ad = g_attdot + (size_t)node * NB;
    float s = 0.f;
#pragma unroll
    for (int b = 0; b < NB; b++) s = fmaf(coef[r * NB + b], ad[b], s);
    g_s[(size_t)node * R + r] = s;
}

// ---------------- fused scatter + score: CSR fill, ex in CSR order, denom atomics ----------------
__global__ __launch_bounds__(256) void k_scatter(const int* __restrict__ src,
                                                 const int* __restrict__ dst,
                                                 const int* __restrict__ rel) {
    int e = blockIdx.x * blockDim.x + threadIdx.x;
    if (e >= N_EDGES) return;
    int sN = src[e], dN = dst[e], rr = rel[e];
    float sc = g_s[(size_t)sN * R + rr] + g_s[(size_t)dN * R + rr];
    sc = (sc >= 0.f) ? sc : 0.01f * sc;
    float ez = expf(sc);
    int pos = atomicAdd(&g_cur[sN], 1);
    g_pk2[pos] = dN * 32 + rr;
    g_w2[pos] = ez;
    atomicAdd(&g_denom[dN], ez);
}

// ---------------- edge pass 2: CSR by src, warp per node ----------------
__global__ __launch_bounds__(256) void k_edge2(const float* __restrict__ coef) {
    int n = (blockIdx.x * blockDim.x + threadIdx.x) >> 5;
    int lane = threadIdx.x & 31;
    if (n >= N_NODES) return;
    int beg = g_off[n], end = g_off[n + 1];
    if (beg == end) return;
    const uint2* xp = (const uint2*)(g_xbh + (size_t)n * (NB * D)) + lane;
    float f[NB][4];
#pragma unroll
    for (int b = 0; b < NB; b++) {
        uint2 u = xp[b * 32];
        float2 f0 = __half22float2(*(const __half2*)&u.x);
        float2 f1 = __half22float2(*(const __half2*)&u.y);
        f[b][0] = f0.x; f[b][1] = f0.y; f[b][2] = f1.x; f[b][3] = f1.y;
    }
#pragma unroll 2
    for (int j = beg; j < end; j++) {
        int pk = g_pk2[j];
        float ez = g_w2[j];
        int dN = pk >> 5, rr = pk & 31;
        float w = ez / g_denom[dN];
        const float4* cp = (const float4*)(coef + rr * NB);
        float4 c0 = cp[0], c1 = cp[1];
        float4 acc;
        acc.x = c0.x * f[0][0]; acc.y = c0.x * f[0][1]; acc.z = c0.x * f[0][2]; acc.w = c0.x * f[0][3];
        acc.x = fmaf(c0.y, f[1][0], acc.x); acc.y = fmaf(c0.y, f[1][1], acc.y);
        acc.z = fmaf(c0.y, f[1][2], acc.z); acc.w = fmaf(c0.y, f[1][3], acc.w);
        acc.x = fmaf(c0.z, f[2][0], acc.x); acc.y = fmaf(c0.z, f[2][1], acc.y);
        acc.z = fmaf(c0.z, f[2][2], acc.z); acc.w = fmaf(c0.z, f[2][3], acc.w);
        acc.x = fmaf(c0.w, f[3][0], acc.x); acc.y = fmaf(c0.w, f[3][1], acc.y);
        acc.z = fmaf(c0.w, f[3][2], acc.z); acc.w = fmaf(c0.w, f[3][3], acc.w);
        acc.x = fmaf(c1.x, f[4][0], acc.x); acc.y = fmaf(c1.x, f[4][1], acc.y);
        acc.z = fmaf(c1.x, f[4][2], acc.z); acc.w = fmaf(c1.x, f[4][3], acc.w);
        acc.x = fmaf(c1.y, f[5][0], acc.x); acc.y = fmaf(c1.y, f[5][1], acc.y);
        acc.z = fmaf(c1.y, f[5][2], acc.z); acc.w = fmaf(c1.y, f[5][3], acc.w);
        acc.x = fmaf(c1.z, f[6][0], acc.x); acc.y = fmaf(c1.z, f[6][1], acc.y);
        acc.z = fmaf(c1.z, f[6][2], acc.z); acc.w = fmaf(c1.z, f[6][3], acc.w);
        acc.x = fmaf(c1.w, f[7][0], acc.x); acc.y = fmaf(c1.w, f[7][1], acc.y);
        acc.z = fmaf(c1.w, f[7][2], acc.z); acc.w = fmaf(c1.w, f[7][3], acc.w);
        acc.x *= w; acc.y *= w; acc.z *= w; acc.w *= w;
        atomicAdd((float4*)(g_accum + (size_t)dN * D + lane * 4), acc);
    }
}

// ---------------- column stats (bias cancels in BN; ft not materialized) ----------------
__global__ __launch_bounds__(128) void k_ft(const float* __restrict__ norm) {
    int o = threadIdx.x;
    float lsum = 0.f, lsq = 0.f;
    for (int n = blockIdx.x; n < N_NODES; n += gridDim.x) {
        float v = g_accum[(size_t)n * D + o] * norm[n] + g_xloop[(size_t)n * D + o];
        lsum += v;
        lsq += v * v;
    }
    atomicAdd(&g_colsum[o], lsum);
    atomicAdd(&g_colsumsq[o], lsq);
}

// ---------------- BN finalize ----------------
__global__ void k_bn(const float* __restrict__ gamma, const float* __restrict__ beta) {
    int o = threadIdx.x;
    float mu = g_colsum[o] / (float)N_NODES;
    float var = g_colsumsq[o] / (float)N_NODES - mu * mu;
    float inv = rsqrtf(var + 1e-5f);
    float sc = gamma[o] * inv;
    g_scale[o] = sc;
    g_shift[o] = beta[o] - mu * sc;
}

// ---------------- output: recompute ft, scale-shift, relu ----------------
__global__ __launch_bounds__(256) void k_out(const float* __restrict__ norm,
                                             float* __restrict__ out) {
    int i = blockIdx.x * blockDim.x + threadIdx.x;
    int total = N_NODES * D / 4;
    if (i >= total) return;
    float nm = norm[(i * 4) >> 7];
    float4 a = ((const float4*)g_accum)[i];
    float4 xl = ((const float4*)g_xloop)[i];
    int o = (i * 4) & (D - 1);
    float4 r;
    r.x = fmaxf(0.f, (a.x * nm + xl.x) * g_scale[o + 0] + g_shift[o + 0]);
    r.y = fmaxf(0.f, (a.y * nm + xl.y) * g_scale[o + 1] + g_shift[o + 1]);
    r.z = fmaxf(0.f, (a.z * nm + xl.z) * g_scale[o + 2] + g_shift[o + 2]);
    r.w = fmaxf(0.f, (a.w * nm + xl.w) * g_scale[o + 3] + g_shift[o + 3]);
    ((float4*)out)[i] = r;
}

extern "C" void kernel_launch(void* const* d_in, const int* in_sizes, int n_in,
                              void* d_out, int out_size) {
    const float* x       = (const float*)d_in[0];
    const float* norm    = (const float*)d_in[1];
    const int*   esrc    = (const int*)d_in[2];
    const int*   edst    = (const int*)d_in[3];
    const int*   erel    = (const int*)d_in[4];
    const float* w_loop  = (const float*)d_in[5];
    const float* w_bases = (const float*)d_in[6];
    const float* coef    = (const float*)d_in[7];
    const float* att     = (const float*)d_in[8];
    // d_in[9] = w_bias: cancels inside BatchNorm, unused
    const float* gamma   = (const float*)d_in[10];
    const float* beta    = (const float*)d_in[11];
    float* out = (float*)d_out;

    cudaFuncSetAttribute(k_gemm_mma, cudaFuncAttributeMaxDynamicSharedMemorySize, SMEM_GEMM);

    k_prep<<<2048, 256>>>(x, w_bases, w_loop);
    k_hist<<<(N_EDGES + 255) / 256, 256>>>(esrc);
    k_scan<<<1, 1024>>>();

    dim3 gg((N_NODES + 127) / 128, 3);
    k_gemm_mma<<<gg, 256, SMEM_GEMM>>>(att);

    k_s2<<<(N_NODES * 32 + 255) / 256, 256>>>(coef);
    k_scatter<<<(N_EDGES + 255) / 256, 256>>>(esrc, edst, erel);
    k_edge2<<<(N_NODES * 32 + 255) / 256, 256>>>(coef);
    k_ft<<<512, 128>>>(norm);
    k_bn<<<1, 128>>>(gamma, beta);
    k_out<<<(N_NODES * D / 4 + 255) / 256, 256>>>(norm, out);
}